// round 6
// baseline (speedup 1.0000x reference)
#include <cuda_runtime.h>
#include <math.h>
#include <stdint.h>

#define Bv    4
#define Tv    2048
#define Dv    1024
#define Hv    16
#define DHv   64
#define HALFv 32
#define MROWS (Bv*Tv)      // 8192
#define NQKV  (3*Dv)       // 3072
#define NKB   (Tv/64)      // 32 key tiles per bh

// ---- scratch (device globals) ----
__device__ float g_q[Bv*Hv*Tv*DHv];     // [b,h,t,dh]
__device__ float g_k[Bv*Hv*Tv*DHv];
__device__ float g_v[Bv*Hv*Tv*DHv];
__device__ float g_attn[MROWS*Dv];      // [b,t,d]
// packed fragments: [bh][kb][fi(64)][lane(32)]
__device__ uint4 g_kpk[64*NKB*64*32];   // (kh0,kh1,kl0,kl1)  67MB
__device__ uint2 g_vpk[64*NKB*64*32];   // (v0,v1)            34MB

__device__ __forceinline__ uint32_t f2tf32(float f) {
    uint32_t u;
    asm("cvt.rna.tf32.f32 %0, %1;" : "=r"(u) : "f"(f));
    return u;
}

__device__ __forceinline__ void mma_tf32(
    float* c, uint32_t a0, uint32_t a1, uint32_t a2, uint32_t a3,
    uint32_t b0, uint32_t b1)
{
    asm volatile(
        "mma.sync.aligned.m16n8k8.row.col.f32.tf32.tf32.f32 "
        "{%0,%1,%2,%3}, {%4,%5,%6,%7}, {%8,%9}, {%0,%1,%2,%3};"
        : "+f"(c[0]), "+f"(c[1]), "+f"(c[2]), "+f"(c[3])
        : "r"(a0), "r"(a1), "r"(a2), "r"(a3), "r"(b0), "r"(b1));
}

// ============================================================================
// tf32 mma.sync dense GEMM (unchanged from R5)
// ============================================================================
#define PITCH 136
#define NCHUNK (Dv / 16)    // 64

template<int MODE>
__global__ __launch_bounds__(256, 2)
void gemm_mma(const float* __restrict__ A, const float* __restrict__ Bw,
              float* __restrict__ C)
{
    __shared__ uint32_t As[2][16][PITCH];
    __shared__ uint32_t Bs[2][16][PITCH];

    const int tid  = threadIdx.x;
    const int wid  = tid >> 5, lane = tid & 31;
    const int gid  = lane >> 2, tg = lane & 3;
    const int wm   = (wid >> 2) * 64;
    const int wn   = (wid & 3) * 32;
    const int m0   = blockIdx.y * 128, n0 = blockIdx.x * 128;

    const int lr = tid & 127, kh = (tid >> 7) * 8;
    const float* gA = A  + (size_t)(m0 + lr) * Dv + kh;
    const float* gB = Bw + (size_t)(n0 + lr) * Dv + kh;

    float acc[4][4][4];
    #pragma unroll
    for (int i = 0; i < 4; i++)
        #pragma unroll
        for (int j = 0; j < 4; j++)
            #pragma unroll
            for (int r = 0; r < 4; r++) acc[i][j][r] = 0.f;

    {
        float4 a0 = *(const float4*)(gA + 0);
        float4 a1 = *(const float4*)(gA + 4);
        float4 b0 = *(const float4*)(gB + 0);
        float4 b1 = *(const float4*)(gB + 4);
        const float av[8] = {a0.x,a0.y,a0.z,a0.w,a1.x,a1.y,a1.z,a1.w};
        const float bv[8] = {b0.x,b0.y,b0.z,b0.w,b1.x,b1.y,b1.z,b1.w};
        #pragma unroll
        for (int j = 0; j < 8; j++) {
            As[0][kh + j][lr] = f2tf32(av[j]);
            Bs[0][kh + j][lr] = f2tf32(bv[j]);
        }
    }
    __syncthreads();

    for (int ch = 0; ch < NCHUNK; ++ch) {
        const int cur = ch & 1;
        float av[8], bv[8];
        if (ch + 1 < NCHUNK) {
            const float* pa = gA + (ch + 1) * 16;
            const float* pb = gB + (ch + 1) * 16;
            float4 t0 = *(const float4*)(pa + 0);
            float4 t1 = *(const float4*)(pa + 4);
            float4 t2 = *(const float4*)(pb + 0);
            float4 t3 = *(const float4*)(pb + 4);
            av[0]=t0.x;av[1]=t0.y;av[2]=t0.z;av[3]=t0.w;
            av[4]=t1.x;av[5]=t1.y;av[6]=t1.z;av[7]=t1.w;
            bv[0]=t2.x;bv[1]=t2.y;bv[2]=t2.z;bv[3]=t2.w;
            bv[4]=t3.x;bv[5]=t3.y;bv[6]=t3.z;bv[7]=t3.w;
        }

        #pragma unroll
        for (int ks = 0; ks < 2; ks++) {
            const int k0 = ks * 8;
            uint32_t af[4][4], bf[4][2];
            #pragma unroll
            for (int mi = 0; mi < 4; mi++) {
                const int mb = wm + mi * 16 + gid;
                af[mi][0] = As[cur][k0 + tg    ][mb];
                af[mi][1] = As[cur][k0 + tg    ][mb + 8];
                af[mi][2] = As[cur][k0 + tg + 4][mb];
                af[mi][3] = As[cur][k0 + tg + 4][mb + 8];
            }
            #pragma unroll
            for (int ni = 0; ni < 4; ni++) {
                const int nb = wn + ni * 8 + gid;
                bf[ni][0] = Bs[cur][k0 + tg    ][nb];
                bf[ni][1] = Bs[cur][k0 + tg + 4][nb];
            }
            #pragma unroll
            for (int mi = 0; mi < 4; mi++)
                #pragma unroll
                for (int ni = 0; ni < 4; ni++)
                    mma_tf32(acc[mi][ni],
                             af[mi][0], af[mi][1], af[mi][2], af[mi][3],
                             bf[ni][0], bf[ni][1]);
        }

        if (ch + 1 < NCHUNK) {
            const int nxt = cur ^ 1;
            #pragma unroll
            for (int j = 0; j < 8; j++) {
                As[nxt][kh + j][lr] = f2tf32(av[j]);
                Bs[nxt][kh + j][lr] = f2tf32(bv[j]);
            }
        }
        __syncthreads();
    }

    #pragma unroll
    for (int mi = 0; mi < 4; mi++) {
        #pragma unroll
        for (int half = 0; half < 2; half++) {
            const int m = m0 + wm + mi * 16 + gid + half * 8;
            const int bb = m >> 11, trow = m & (Tv - 1);
            #pragma unroll
            for (int ni = 0; ni < 4; ni++) {
                const int n = n0 + wn + ni * 8 + tg * 2;
                float2 val;
                val.x = acc[mi][ni][half * 2 + 0];
                val.y = acc[mi][ni][half * 2 + 1];
                if (MODE == 0) {
                    const int wh = n >> 10;
                    const int d  = n & (Dv - 1);
                    const int h  = d >> 6, dd = d & 63;
                    float* dst = ((wh == 0) ? g_q : (wh == 1) ? g_k : g_v)
                               + ((size_t)(bb * Hv + h) * Tv + trow) * DHv + dd;
                    *(float2*)dst = val;
                } else {
                    *(float2*)(C + (size_t)m * Dv + n) = val;
                }
            }
        }
    }
}

// ============================================================================
// RoPE on g_q and g_k in place.
// ============================================================================
__global__ void rope_kernel(const float* __restrict__ cosT,
                            const float* __restrict__ sinT)
{
    int gid = blockIdx.x * blockDim.x + threadIdx.x;
    if (gid >= Bv*Hv*Tv*HALFv) return;
    int i   = gid & (HALFv - 1);
    int row = gid >> 5;
    int t   = row & (Tv - 1);
    float c = cosT[t*HALFv + i];
    float s = sinT[t*HALFv + i];

    float* qp = g_q + (size_t)row * DHv;
    float q1 = qp[i], q2 = qp[i + HALFv];
    qp[i]          = q1*c - q2*s;
    qp[i + HALFv]  = q1*s + q2*c;

    float* kp = g_k + (size_t)row * DHv;
    float k1 = kp[i], k2 = kp[i + HALFv];
    kp[i]          = k1*c - k2*s;
    kp[i + HALFv]  = k1*s + k2*c;
}

// ============================================================================
// Pack K (hi/lo tf32 split) and V into mma b-fragment order (post-RoPE).
// Entry (bh, kb, fi=ks*8+nf, lane=(gid,tg)):
//   K: uint4( tf32h(K[key][dh]), tf32h(K[key][dh+4]), lo, lo )
//      key = kb*64+nf*8+gid, dh = ks*8+tg
//   V: uint2( tf32(V[cs*8+tg][df*8+gid]), tf32(V[cs*8+tg+4][df*8+gid]) )
// ============================================================================
__global__ __launch_bounds__(256)
void pack_kv()
{
    const int kb = blockIdx.x, bh = blockIdx.y;
    const size_t base = ((size_t)(bh * NKB + kb)) * 64 * 32;
    const size_t rowbase = (size_t)bh * Tv + kb * 64;

    #pragma unroll
    for (int i = 0; i < 8; i++) {
        int e = threadIdx.x + i * 256;      // 0..2047
        int lane = e & 31, fi = e >> 5;
        int gid = lane >> 2, tg = lane & 3;
        int ks = fi >> 3, nf = fi & 7;

        // K fragment
        const float* kp = g_k + (rowbase + nf*8 + gid) * DHv + ks*8 + tg;
        float x0 = kp[0], x1 = kp[4];
        uint32_t h0 = f2tf32(x0), h1 = f2tf32(x1);
        g_kpk[base + (size_t)fi*32 + lane] =
            make_uint4(h0, h1, f2tf32(x0 - __uint_as_float(h0)),
                               f2tf32(x1 - __uint_as_float(h1)));

        // V fragment (cs = ks, df = nf)
        const float* vp = g_v + (rowbase + ks*8 + tg) * DHv + nf*8 + gid;
        g_vpk[base + (size_t)fi*32 + lane] =
            make_uint2(f2tf32(vp[0]), f2tf32(vp[4*DHv]));
    }
}

// ============================================================================
// Flash attention: barrier-free mainloop, fragments LDG'd from g_kpk/g_vpk.
// q-tile 128 (8 warps x 16 rows), key-tile 64/iter.
// QK^T 3xtf32, PV tf32. Diagonal kept in denom, zeroed in P.
// Smem 98304B: Qhip[8w][8ks][32]u4 @0, Qlop @32768, Ppk[8w][8][32]f4 @65536.
// All regions warp-private -> only __syncwarp in loop. 2 CTAs/SM.
// ============================================================================
#define ATTN_SMEM (3*32768)

__global__ __launch_bounds__(256, 2)
void attn_mma()
{
    extern __shared__ char sm[];
    uint4*  Qhip = (uint4*)sm;
    uint4*  Qlop = (uint4*)(sm + 32768);
    float4* Ppk  = (float4*)(sm + 65536);

    const int qb = (int)gridDim.x - 1 - (int)blockIdx.x;  // heavy tiles first
    const int bh = blockIdx.y;
    const int tid = threadIdx.x;
    const int w = tid >> 5, lane = tid & 31;
    const int gid = lane >> 2, tg = lane & 3;

    const int rowA = qb*128 + 16*w + gid;
    const int rowB = rowA + 8;

    // ---- Q fragments (scaled, hi/lo) -> warp-private smem ----
    {
        const float* qA = g_q + ((size_t)bh*Tv + rowA) * DHv + tg;
        const float* qB = qA + 8 * DHv;
        #pragma unroll
        for (int ks = 0; ks < 8; ks++) {
            float q0 = qA[ks*8    ] * 0.125f;
            float q1 = qB[ks*8    ] * 0.125f;
            float q2 = qA[ks*8 + 4] * 0.125f;
            float q3 = qB[ks*8 + 4] * 0.125f;
            uint32_t h0 = f2tf32(q0), h1 = f2tf32(q1);
            uint32_t h2 = f2tf32(q2), h3 = f2tf32(q3);
            Qhip[(w*8 + ks)*32 + lane] = make_uint4(h0, h1, h2, h3);
            Qlop[(w*8 + ks)*32 + lane] =
                make_uint4(f2tf32(q0 - __uint_as_float(h0)),
                           f2tf32(q1 - __uint_as_float(h1)),
                           f2tf32(q2 - __uint_as_float(h2)),
                           f2tf32(q3 - __uint_as_float(h3)));
        }
    }
    __syncwarp();

    float O[8][4];
    #pragma unroll
    for (int d = 0; d < 8; d++)
        #pragma unroll
        for (int r = 0; r < 4; r++) O[d][r] = 0.f;
    float m0 = -1e30f, m1 = -1e30f, l0 = 0.f, l1 = 0.f;

    const uint4* kpk = g_kpk + (size_t)bh * NKB * 2048 + lane;
    const uint2* vpk = g_vpk + (size_t)bh * NKB * 2048 + lane;

    const int niter = 2 * (qb + 1);
    for (int j = 0; j < niter; j++) {
        const int k0g = j * 64;
        const uint4* kt = kpk + (size_t)j * 2048;
        const uint2* vt = vpk + (size_t)j * 2048;

        // ---- S = Q K^T (3xtf32) ----
        float S[8][4];
        #pragma unroll
        for (int nf = 0; nf < 8; nf++)
            #pragma unroll
            for (int r = 0; r < 4; r++) S[nf][r] = 0.f;
        #pragma unroll
        for (int ks = 0; ks < 8; ks++) {
            uint4 qh = Qhip[(w*8 + ks)*32 + lane];
            uint4 ql = Qlop[(w*8 + ks)*32 + lane];
            #pragma unroll
            for (int nf = 0; nf < 8; nf++) {
                uint4 kf = kt[(ks*8 + nf)*32];
                mma_tf32(S[nf], qh.x, qh.y, qh.z, qh.w, kf.x, kf.y);
                mma_tf32(S[nf], ql.x, ql.y, ql.z, ql.w, kf.x, kf.y);
                mma_tf32(S[nf], qh.x, qh.y, qh.z, qh.w, kf.z, kf.w);
            }
        }

        // ---- mask + online softmax ----
        float mxA = -1e30f, mxB = -1e30f;
        #pragma unroll
        for (int nf = 0; nf < 8; nf++) {
            const int cA = k0g + nf*8 + 2*tg, cB = cA + 1;
            if (cA > rowA) S[nf][0] = -1e30f;
            if (cB > rowA) S[nf][1] = -1e30f;
            if (cA > rowB) S[nf][2] = -1e30f;
            if (cB > rowB) S[nf][3] = -1e30f;
            mxA = fmaxf(mxA, fmaxf(S[nf][0], S[nf][1]));
            mxB = fmaxf(mxB, fmaxf(S[nf][2], S[nf][3]));
        }
        mxA = fmaxf(mxA, __shfl_xor_sync(0xffffffffu, mxA, 1));
        mxA = fmaxf(mxA, __shfl_xor_sync(0xffffffffu, mxA, 2));
        mxB = fmaxf(mxB, __shfl_xor_sync(0xffffffffu, mxB, 1));
        mxB = fmaxf(mxB, __shfl_xor_sync(0xffffffffu, mxB, 2));
        const float mnA = fmaxf(m0, mxA), mnB = fmaxf(m1, mxB);
        const float corrA = __expf(m0 - mnA), corrB = __expf(m1 - mnB);

        float sA = 0.f, sB = 0.f;
        #pragma unroll
        for (int nf = 0; nf < 8; nf++) {
            const int cA = k0g + nf*8 + 2*tg, cB = cA + 1;
            float e0 = __expf(S[nf][0] - mnA);
            float e1 = __expf(S[nf][1] - mnA);
            float e2 = __expf(S[nf][2] - mnB);
            float e3 = __expf(S[nf][3] - mnB);
            sA += e0 + e1; sB += e2 + e3;
            if (cA == rowA) e0 = 0.f;
            if (cB == rowA) e1 = 0.f;
            if (cA == rowB) e2 = 0.f;
            if (cB == rowB) e3 = 0.f;
            {
                const int c0p = 2*tg;
                char* b = (char*)&Ppk[(w*8 + nf)*32 + 4*gid + (c0p & 3)];
                *(uint2*)(b + ((c0p < 4) ? 0 : 8)) = make_uint2(f2tf32(e0), f2tf32(e2));
            }
            {
                const int c1p = 2*tg + 1;
                char* b = (char*)&Ppk[(w*8 + nf)*32 + 4*gid + (c1p & 3)];
                *(uint2*)(b + ((c1p < 4) ? 0 : 8)) = make_uint2(f2tf32(e1), f2tf32(e3));
            }
        }
        sA += __shfl_xor_sync(0xffffffffu, sA, 1);
        sA += __shfl_xor_sync(0xffffffffu, sA, 2);
        sB += __shfl_xor_sync(0xffffffffu, sB, 1);
        sB += __shfl_xor_sync(0xffffffffu, sB, 2);
        l0 = l0 * corrA + sA;  m0 = mnA;
        l1 = l1 * corrB + sB;  m1 = mnB;
        #pragma unroll
        for (int d = 0; d < 8; d++) {
            O[d][0] *= corrA; O[d][1] *= corrA;
            O[d][2] *= corrB; O[d][3] *= corrB;
        }
        __syncwarp();

        // ---- O += P V (tf32) ----
        #pragma unroll
        for (int cs = 0; cs < 8; cs++) {
            uint4 a = *(const uint4*)&Ppk[(w*8 + cs)*32 + lane];
            #pragma unroll
            for (int df = 0; df < 8; df++) {
                uint2 b = vt[(cs*8 + df)*32];
                mma_tf32(O[df], a.x, a.y, a.z, a.w, b.x, b.y);
            }
        }
        __syncwarp();
    }

    // ---- epilogue ----
    const int bb = bh >> 4, h = bh & 15;
    const float inv0 = 1.f / l0, inv1 = 1.f / l1;
    #pragma unroll
    for (int df = 0; df < 8; df++) {
        const int col = h*64 + df*8 + 2*tg;
        float2 vA = make_float2(O[df][0] * inv0, O[df][1] * inv0);
        float2 vB = make_float2(O[df][2] * inv1, O[df][3] * inv1);
        *(float2*)&g_attn[((size_t)bb*Tv + rowA) * Dv + col] = vA;
        *(float2*)&g_attn[((size_t)bb*Tv + rowB) * Dv + col] = vB;
    }
}

// ============================================================================
extern "C" void kernel_launch(void* const* d_in, const int* in_sizes, int n_in,
                              void* d_out, int out_size)
{
    const float* x     = (const float*)d_in[0];
    const float* cosT  = (const float*)d_in[1];
    const float* sinT  = (const float*)d_in[2];
    const float* Wqkv  = (const float*)d_in[3];
    const float* Wproj = (const float*)d_in[4];

    float* attn_ptr = nullptr;
    cudaGetSymbolAddress((void**)&attn_ptr, g_attn);

    cudaFuncSetAttribute(attn_mma, cudaFuncAttributeMaxDynamicSharedMemorySize, ATTN_SMEM);

    // 1) QKV projection (tf32 mma.sync), scattered into [b,h,t,dh]
    gemm_mma<0><<<dim3(NQKV/128, MROWS/128), 256>>>(x, Wqkv, nullptr);
    // 2) RoPE on q,k
    rope_kernel<<<(Bv*Hv*Tv*HALFv + 255)/256, 256>>>(cosT, sinT);
    // 3) pack K/V into mma fragment order
    pack_kv<<<dim3(NKB, Bv*Hv), 256>>>();
    // 4) causal attention on tensor cores (barrier-free mainloop)
    attn_mma<<<dim3(Tv/128, Bv*Hv), 256, ATTN_SMEM>>>();
    // 5) output projection (tf32 mma.sync) -> d_out
    gemm_mma<1><<<dim3(Dv/128, MROWS/128), 256>>>(attn_ptr, Wproj, (float*)d_out);
}

// round 7
// speedup vs baseline: 1.6181x; 1.6181x over previous
#include <cuda_runtime.h>
#include <math.h>
#include <stdint.h>

#define Bv    4
#define Tv    2048
#define Dv    1024
#define Hv    16
#define DHv   64
#define HALFv 32
#define MROWS (Bv*Tv)      // 8192
#define NQKV  (3*Dv)       // 3072
#define NKB   (Tv/64)      // 32 key tiles per bh

// ---- scratch (device globals) ----
__device__ float g_q[Bv*Hv*Tv*DHv];     // [b,h,t,dh] fp32 (RoPE needs full precision)
__device__ float g_k[Bv*Hv*Tv*DHv];
__device__ float g_v[Bv*Hv*Tv*DHv];
__device__ float g_attn[MROWS*Dv];      // [b,t,d], tf32-rounded by attn epilogue
__device__ float g_xr[MROWS*Dv];        // tf32-rounded x
__device__ float g_wqkvr[NQKV*Dv];      // tf32-rounded W_qkv
__device__ float g_wprojr[Dv*Dv];       // tf32-rounded W_proj
// packed fragments: [bh][kb][fi(64)][lane(32)]
__device__ uint2 g_kpk[64*NKB*64*32];   // (kh0,kh1)  K hi fragments
__device__ uint2 g_vpk[64*NKB*64*32];   // (v0,v1)    V fragments

__device__ __forceinline__ uint32_t f2tf32(float f) {
    uint32_t u;
    asm("cvt.rna.tf32.f32 %0, %1;" : "=r"(u) : "f"(f));
    return u;
}

__device__ __forceinline__ void mma_tf32(
    float* c, uint32_t a0, uint32_t a1, uint32_t a2, uint32_t a3,
    uint32_t b0, uint32_t b1)
{
    asm volatile(
        "mma.sync.aligned.m16n8k8.row.col.f32.tf32.tf32.f32 "
        "{%0,%1,%2,%3}, {%4,%5,%6,%7}, {%8,%9}, {%0,%1,%2,%3};"
        : "+f"(c[0]), "+f"(c[1]), "+f"(c[2]), "+f"(c[3])
        : "r"(a0), "r"(a1), "r"(a2), "r"(a3), "r"(b0), "r"(b1));
}

__device__ __forceinline__ uint32_t smem_u32(const void* p) {
    uint32_t a;
    asm("{ .reg .u64 t; cvta.to.shared.u64 t, %1; cvt.u32.u64 %0, t; }"
        : "=r"(a) : "l"(p));
    return a;
}

#define CP_ASYNC16(dst_u32, src) \
    asm volatile("cp.async.cg.shared.global [%0], [%1], 16;" \
                 :: "r"(dst_u32), "l"(src) : "memory")
#define CP_COMMIT() asm volatile("cp.async.commit_group;" ::: "memory")
#define CP_WAIT1()  asm volatile("cp.async.wait_group 1;" ::: "memory")

// ============================================================================
// Round fp32 -> tf32 (RNA), stored as fp32 bits (low 13 bits zero).
// ============================================================================
__global__ void round_tf32(const float* __restrict__ in, float* __restrict__ out,
                           int n)
{
    int i = (blockIdx.x * blockDim.x + threadIdx.x) * 4;
    if (i >= n) return;
    float4 v = *(const float4*)(in + i);
    v.x = __uint_as_float(f2tf32(v.x));
    v.y = __uint_as_float(f2tf32(v.y));
    v.z = __uint_as_float(f2tf32(v.z));
    v.w = __uint_as_float(f2tf32(v.w));
    *(float4*)(out + i) = v;
}

// ============================================================================
// cp.async 3-stage tf32 GEMM: C[M,N] = A[M,K]*Bw[N,K]^T, K=1024.
// Inputs pre-rounded to tf32 (fp32 bits) -> no cvt in hot loop.
// CTA 128x128, 8 warps, warp 64x32, K-chunk 16, stages 3.
// smem per stage: A[128][20] + B[128][20] floats (pitch 20 = 16B-aligned,
// conflict-free fragment banks). 60KB total dynamic.
// MODE 0: scatter fp32 into g_q/g_k/g_v. MODE 1: row-major C.
// ============================================================================
#define GP        20
#define SSTRIDE   (2*128*GP)           // floats per stage = 5120
#define GEMM_SMEM (3*SSTRIDE*4)        // 61440 B
#define NCH       (Dv/16)              // 64

template<int MODE>
__global__ __launch_bounds__(256, 2)
void gemm_cp(const float* __restrict__ A, const float* __restrict__ Bw,
             float* __restrict__ C)
{
    extern __shared__ float smf[];
    const uint32_t sb32 = smem_u32(smf);

    const int tid  = threadIdx.x;
    const int wid  = tid >> 5, lane = tid & 31;
    const int gid  = lane >> 2, tg = lane & 3;
    const int wm   = (wid >> 2) * 64;
    const int wn   = (wid & 3) * 32;
    const int m0   = blockIdx.y * 128, n0 = blockIdx.x * 128;

    // copy assignment: e in {tid, tid+256}: row = e>>2, 16B-chunk c4 = e&3
    const int r0 = tid >> 2, c4 = (tid & 3) * 4;
    const float* gA0 = A  + (size_t)(m0 + r0) * Dv + c4;
    const float* gA1 = gA0 + (size_t)64 * Dv;
    const float* gB0 = Bw + (size_t)(n0 + r0) * Dv + c4;
    const float* gB1 = gB0 + (size_t)64 * Dv;
    const uint32_t dA0 = sb32 + (r0*GP + c4) * 4;
    const uint32_t dA1 = dA0 + 64*GP*4;
    const uint32_t dB0 = dA0 + 2560*4;
    const uint32_t dB1 = dB0 + 64*GP*4;

    float acc[4][4][4];
    #pragma unroll
    for (int i = 0; i < 4; i++)
        #pragma unroll
        for (int j = 0; j < 4; j++)
            #pragma unroll
            for (int r = 0; r < 4; r++) acc[i][j][r] = 0.f;

    // prologue: stages 0,1
    #pragma unroll
    for (int p = 0; p < 2; p++) {
        const uint32_t so = p * SSTRIDE * 4;
        const int ko = p * 16;
        CP_ASYNC16(dA0 + so, gA0 + ko);
        CP_ASYNC16(dA1 + so, gA1 + ko);
        CP_ASYNC16(dB0 + so, gB0 + ko);
        CP_ASYNC16(dB1 + so, gB1 + ko);
        CP_COMMIT();
    }

    int st = 0;
    for (int ch = 0; ch < NCH; ++ch) {
        CP_WAIT1();
        __syncthreads();

        // prefetch ch+2
        if (ch + 2 < NCH) {
            const int pst = (st + 2 >= 3) ? st - 1 : st + 2;
            const uint32_t so = pst * SSTRIDE * 4;
            const int ko = (ch + 2) * 16;
            CP_ASYNC16(dA0 + so, gA0 + ko);
            CP_ASYNC16(dA1 + so, gA1 + ko);
            CP_ASYNC16(dB0 + so, gB0 + ko);
            CP_ASYNC16(dB1 + so, gB1 + ko);
        }
        CP_COMMIT();

        const uint32_t* Sa = (const uint32_t*)(smf + st * SSTRIDE);
        const uint32_t* Sbq = Sa + 2560;

        #pragma unroll
        for (int ks = 0; ks < 2; ks++) {
            const int k0 = ks * 8;
            uint32_t af[4][4], bf[4][2];
            #pragma unroll
            for (int mi = 0; mi < 4; mi++) {
                const int mb = wm + mi * 16 + gid;
                af[mi][0] = Sa[ mb      * GP + k0 + tg    ];
                af[mi][1] = Sa[(mb + 8) * GP + k0 + tg    ];
                af[mi][2] = Sa[ mb      * GP + k0 + tg + 4];
                af[mi][3] = Sa[(mb + 8) * GP + k0 + tg + 4];
            }
            #pragma unroll
            for (int ni = 0; ni < 4; ni++) {
                const int nb = wn + ni * 8 + gid;
                bf[ni][0] = Sbq[nb * GP + k0 + tg    ];
                bf[ni][1] = Sbq[nb * GP + k0 + tg + 4];
            }
            #pragma unroll
            for (int mi = 0; mi < 4; mi++)
                #pragma unroll
                for (int ni = 0; ni < 4; ni++)
                    mma_tf32(acc[mi][ni],
                             af[mi][0], af[mi][1], af[mi][2], af[mi][3],
                             bf[ni][0], bf[ni][1]);
        }
        st = (st + 1 == 3) ? 0 : st + 1;
    }

    // ---- epilogue ----
    #pragma unroll
    for (int mi = 0; mi < 4; mi++) {
        #pragma unroll
        for (int half = 0; half < 2; half++) {
            const int m = m0 + wm + mi * 16 + gid + half * 8;
            const int bb = m >> 11, trow = m & (Tv - 1);
            #pragma unroll
            for (int ni = 0; ni < 4; ni++) {
                const int n = n0 + wn + ni * 8 + tg * 2;
                float2 val;
                val.x = acc[mi][ni][half * 2 + 0];
                val.y = acc[mi][ni][half * 2 + 1];
                if (MODE == 0) {
                    const int wh = n >> 10;
                    const int d  = n & (Dv - 1);
                    const int h  = d >> 6, dd = d & 63;
                    float* dst = ((wh == 0) ? g_q : (wh == 1) ? g_k : g_v)
                               + ((size_t)(bb * Hv + h) * Tv + trow) * DHv + dd;
                    *(float2*)dst = val;
                } else {
                    *(float2*)(C + (size_t)m * Dv + n) = val;
                }
            }
        }
    }
}

// ============================================================================
// RoPE on g_q and g_k in place.
// ============================================================================
__global__ void rope_kernel(const float* __restrict__ cosT,
                            const float* __restrict__ sinT)
{
    int gid = blockIdx.x * blockDim.x + threadIdx.x;
    if (gid >= Bv*Hv*Tv*HALFv) return;
    int i   = gid & (HALFv - 1);
    int row = gid >> 5;
    int t   = row & (Tv - 1);
    float c = cosT[t*HALFv + i];
    float s = sinT[t*HALFv + i];

    float* qp = g_q + (size_t)row * DHv;
    float q1 = qp[i], q2 = qp[i + HALFv];
    qp[i]          = q1*c - q2*s;
    qp[i + HALFv]  = q1*s + q2*c;

    float* kp = g_k + (size_t)row * DHv;
    float k1 = kp[i], k2 = kp[i + HALFv];
    kp[i]          = k1*c - k2*s;
    kp[i + HALFv]  = k1*s + k2*c;
}

// ============================================================================
// Pack K (tf32 hi) and V into mma b-fragment order (post-RoPE).
// ============================================================================
__global__ __launch_bounds__(256)
void pack_kv()
{
    const int kb = blockIdx.x, bh = blockIdx.y;
    const size_t base = ((size_t)(bh * NKB + kb)) * 64 * 32;
    const size_t rowbase = (size_t)bh * Tv + kb * 64;

    #pragma unroll
    for (int i = 0; i < 8; i++) {
        int e = threadIdx.x + i * 256;      // 0..2047
        int lane = e & 31, fi = e >> 5;
        int gid = lane >> 2, tg = lane & 3;
        int ks = fi >> 3, nf = fi & 7;

        // K fragment (hi only)
        const float* kp = g_k + (rowbase + nf*8 + gid) * DHv + ks*8 + tg;
        g_kpk[base + (size_t)fi*32 + lane] =
            make_uint2(f2tf32(kp[0]), f2tf32(kp[4]));

        // V fragment (cs = ks, df = nf)
        const float* vp = g_v + (rowbase + ks*8 + tg) * DHv + nf*8 + gid;
        g_vpk[base + (size_t)fi*32 + lane] =
            make_uint2(f2tf32(vp[0]), f2tf32(vp[4*DHv]));
    }
}

// ============================================================================
// Flash attention: barrier-free mainloop, fragments LDG'd from g_kpk/g_vpk.
// QK^T 2-term split (q_hi*k + q_lo*k), PV tf32. Diagonal kept in denom,
// zeroed in P. Epilogue rounds output to tf32 for the proj GEMM.
// ============================================================================
#define ATTN_SMEM (3*32768)

__global__ __launch_bounds__(256, 2)
void attn_mma()
{
    extern __shared__ char sm[];
    uint4*  Qhip = (uint4*)sm;
    uint4*  Qlop = (uint4*)(sm + 32768);
    float4* Ppk  = (float4*)(sm + 65536);

    const int qb = (int)gridDim.x - 1 - (int)blockIdx.x;  // heavy tiles first
    const int bh = blockIdx.y;
    const int tid = threadIdx.x;
    const int w = tid >> 5, lane = tid & 31;
    const int gid = lane >> 2, tg = lane & 3;

    const int rowA = qb*128 + 16*w + gid;
    const int rowB = rowA + 8;

    // ---- Q fragments (scaled, hi/lo) -> warp-private smem ----
    {
        const float* qA = g_q + ((size_t)bh*Tv + rowA) * DHv + tg;
        const float* qB = qA + 8 * DHv;
        #pragma unroll
        for (int ks = 0; ks < 8; ks++) {
            float q0 = qA[ks*8    ] * 0.125f;
            float q1 = qB[ks*8    ] * 0.125f;
            float q2 = qA[ks*8 + 4] * 0.125f;
            float q3 = qB[ks*8 + 4] * 0.125f;
            uint32_t h0 = f2tf32(q0), h1 = f2tf32(q1);
            uint32_t h2 = f2tf32(q2), h3 = f2tf32(q3);
            Qhip[(w*8 + ks)*32 + lane] = make_uint4(h0, h1, h2, h3);
            Qlop[(w*8 + ks)*32 + lane] =
                make_uint4(f2tf32(q0 - __uint_as_float(h0)),
                           f2tf32(q1 - __uint_as_float(h1)),
                           f2tf32(q2 - __uint_as_float(h2)),
                           f2tf32(q3 - __uint_as_float(h3)));
        }
    }
    __syncwarp();

    float O[8][4];
    #pragma unroll
    for (int d = 0; d < 8; d++)
        #pragma unroll
        for (int r = 0; r < 4; r++) O[d][r] = 0.f;
    float m0 = -1e30f, m1 = -1e30f, l0 = 0.f, l1 = 0.f;

    const uint2* kpk = g_kpk + (size_t)bh * NKB * 2048 + lane;
    const uint2* vpk = g_vpk + (size_t)bh * NKB * 2048 + lane;

    const int niter = 2 * (qb + 1);
    for (int j = 0; j < niter; j++) {
        const int k0g = j * 64;
        const uint2* kt = kpk + (size_t)j * 2048;
        const uint2* vt = vpk + (size_t)j * 2048;

        // ---- S = Q K^T (2-term split) ----
        float S[8][4];
        #pragma unroll
        for (int nf = 0; nf < 8; nf++)
            #pragma unroll
            for (int r = 0; r < 4; r++) S[nf][r] = 0.f;
        #pragma unroll
        for (int ks = 0; ks < 8; ks++) {
            uint4 qh = Qhip[(w*8 + ks)*32 + lane];
            uint4 ql = Qlop[(w*8 + ks)*32 + lane];
            #pragma unroll
            for (int nf = 0; nf < 8; nf++) {
                uint2 kf = kt[(ks*8 + nf)*32];
                mma_tf32(S[nf], qh.x, qh.y, qh.z, qh.w, kf.x, kf.y);
                mma_tf32(S[nf], ql.x, ql.y, ql.z, ql.w, kf.x, kf.y);
            }
        }

        // ---- mask + online softmax ----
        float mxA = -1e30f, mxB = -1e30f;
        #pragma unroll
        for (int nf = 0; nf < 8; nf++) {
            const int cA = k0g + nf*8 + 2*tg, cB = cA + 1;
            if (cA > rowA) S[nf][0] = -1e30f;
            if (cB > rowA) S[nf][1] = -1e30f;
            if (cA > rowB) S[nf][2] = -1e30f;
            if (cB > rowB) S[nf][3] = -1e30f;
            mxA = fmaxf(mxA, fmaxf(S[nf][0], S[nf][1]));
            mxB = fmaxf(mxB, fmaxf(S[nf][2], S[nf][3]));
        }
        mxA = fmaxf(mxA, __shfl_xor_sync(0xffffffffu, mxA, 1));
        mxA = fmaxf(mxA, __shfl_xor_sync(0xffffffffu, mxA, 2));
        mxB = fmaxf(mxB, __shfl_xor_sync(0xffffffffu, mxB, 1));
        mxB = fmaxf(mxB, __shfl_xor_sync(0xffffffffu, mxB, 2));
        const float mnA = fmaxf(m0, mxA), mnB = fmaxf(m1, mxB);
        const float corrA = __expf(m0 - mnA), corrB = __expf(m1 - mnB);

        float sA = 0.f, sB = 0.f;
        #pragma unroll
        for (int nf = 0; nf < 8; nf++) {
            const int cA = k0g + nf*8 + 2*tg, cB = cA + 1;
            float e0 = __expf(S[nf][0] - mnA);
            float e1 = __expf(S[nf][1] - mnA);
            float e2 = __expf(S[nf][2] - mnB);
            float e3 = __expf(S[nf][3] - mnB);
            sA += e0 + e1; sB += e2 + e3;
            if (cA == rowA) e0 = 0.f;
            if (cB == rowA) e1 = 0.f;
            if (cA == rowB) e2 = 0.f;
            if (cB == rowB) e3 = 0.f;
            {
                const int c0p = 2*tg;
                char* b = (char*)&Ppk[(w*8 + nf)*32 + 4*gid + (c0p & 3)];
                *(uint2*)(b + ((c0p < 4) ? 0 : 8)) = make_uint2(f2tf32(e0), f2tf32(e2));
            }
            {
                const int c1p = 2*tg + 1;
                char* b = (char*)&Ppk[(w*8 + nf)*32 + 4*gid + (c1p & 3)];
                *(uint2*)(b + ((c1p < 4) ? 0 : 8)) = make_uint2(f2tf32(e1), f2tf32(e3));
            }
        }
        sA += __shfl_xor_sync(0xffffffffu, sA, 1);
        sA += __shfl_xor_sync(0xffffffffu, sA, 2);
        sB += __shfl_xor_sync(0xffffffffu, sB, 1);
        sB += __shfl_xor_sync(0xffffffffu, sB, 2);
        l0 = l0 * corrA + sA;  m0 = mnA;
        l1 = l1 * corrB + sB;  m1 = mnB;
        #pragma unroll
        for (int d = 0; d < 8; d++) {
            O[d][0] *= corrA; O[d][1] *= corrA;
            O[d][2] *= corrB; O[d][3] *= corrB;
        }
        __syncwarp();

        // ---- O += P V (tf32) ----
        #pragma unroll
        for (int cs = 0; cs < 8; cs++) {
            uint4 a = *(const uint4*)&Ppk[(w*8 + cs)*32 + lane];
            #pragma unroll
            for (int df = 0; df < 8; df++) {
                uint2 b = vt[(cs*8 + df)*32];
                mma_tf32(O[df], a.x, a.y, a.z, a.w, b.x, b.y);
            }
        }
        __syncwarp();
    }

    // ---- epilogue (round to tf32 for the proj GEMM) ----
    const int bb = bh >> 4, h = bh & 15;
    const float inv0 = 1.f / l0, inv1 = 1.f / l1;
    #pragma unroll
    for (int df = 0; df < 8; df++) {
        const int col = h*64 + df*8 + 2*tg;
        float2 vA, vB;
        vA.x = __uint_as_float(f2tf32(O[df][0] * inv0));
        vA.y = __uint_as_float(f2tf32(O[df][1] * inv0));
        vB.x = __uint_as_float(f2tf32(O[df][2] * inv1));
        vB.y = __uint_as_float(f2tf32(O[df][3] * inv1));
        *(float2*)&g_attn[((size_t)bb*Tv + rowA) * Dv + col] = vA;
        *(float2*)&g_attn[((size_t)bb*Tv + rowB) * Dv + col] = vB;
    }
}

// ============================================================================
extern "C" void kernel_launch(void* const* d_in, const int* in_sizes, int n_in,
                              void* d_out, int out_size)
{
    const float* x     = (const float*)d_in[0];
    const float* cosT  = (const float*)d_in[1];
    const float* sinT  = (const float*)d_in[2];
    const float* Wqkv  = (const float*)d_in[3];
    const float* Wproj = (const float*)d_in[4];

    float *attn_ptr, *xr_ptr, *wqkvr_ptr, *wprojr_ptr;
    cudaGetSymbolAddress((void**)&attn_ptr,   g_attn);
    cudaGetSymbolAddress((void**)&xr_ptr,     g_xr);
    cudaGetSymbolAddress((void**)&wqkvr_ptr,  g_wqkvr);
    cudaGetSymbolAddress((void**)&wprojr_ptr, g_wprojr);

    cudaFuncSetAttribute(attn_mma, cudaFuncAttributeMaxDynamicSharedMemorySize, ATTN_SMEM);
    cudaFuncSetAttribute(gemm_cp<0>, cudaFuncAttributeMaxDynamicSharedMemorySize, GEMM_SMEM);
    cudaFuncSetAttribute(gemm_cp<1>, cudaFuncAttributeMaxDynamicSharedMemorySize, GEMM_SMEM);

    // 0) pre-round GEMM inputs to tf32
    round_tf32<<<MROWS*Dv/1024, 256>>>(x, xr_ptr, MROWS*Dv);
    round_tf32<<<NQKV*Dv/1024, 256>>>(Wqkv, wqkvr_ptr, NQKV*Dv);
    round_tf32<<<Dv*Dv/1024, 256>>>(Wproj, wprojr_ptr, Dv*Dv);

    // 1) QKV projection (cp.async tf32 mma), scattered into [b,h,t,dh]
    gemm_cp<0><<<dim3(NQKV/128, MROWS/128), 256, GEMM_SMEM>>>(xr_ptr, wqkvr_ptr, nullptr);
    // 2) RoPE on q,k
    rope_kernel<<<(Bv*Hv*Tv*HALFv + 255)/256, 256>>>(cosT, sinT);
    // 3) pack K/V into mma fragment order
    pack_kv<<<dim3(NKB, Bv*Hv), 256>>>();
    // 4) causal attention on tensor cores (barrier-free mainloop)
    attn_mma<<<dim3(Tv/128, Bv*Hv), 256, ATTN_SMEM>>>();
    // 5) output projection -> d_out
    gemm_cp<1><<<dim3(Dv/128, MROWS/128), 256, GEMM_SMEM>>>(attn_ptr, wprojr_ptr, (float*)d_out);
}

// round 8
// speedup vs baseline: 1.8066x; 1.1165x over previous
#include <cuda_runtime.h>
#include <math.h>
#include <stdint.h>

#define Bv    4
#define Tv    2048
#define Dv    1024
#define Hv    16
#define DHv   64
#define HALFv 32
#define MROWS (Bv*Tv)      // 8192
#define NQKV  (3*Dv)       // 3072
#define NKB   (Tv/64)      // 32 key tiles per bh

// ---- scratch (device globals) ----
__device__ float g_q[Bv*Hv*Tv*DHv];     // [b,h,t,dh] fp32
__device__ float g_k[Bv*Hv*Tv*DHv];
__device__ float g_v[Bv*Hv*Tv*DHv];
__device__ float g_attn[MROWS*Dv];      // [b,t,d], tf32-rounded by attn epilogue
__device__ float g_xr[MROWS*Dv];        // tf32-rounded x
__device__ float g_wqkvr[NQKV*Dv];      // tf32-rounded W_qkv
__device__ float g_wprojr[Dv*Dv];       // tf32-rounded W_proj
// packed fragments: [bh][kb][fi(64)][lane(32)]
__device__ uint2 g_kpk[64*NKB*64*32];   // (kh0,kh1)  K hi fragments
__device__ uint2 g_vpk[64*NKB*64*32];   // (v0,v1)    V fragments

__device__ __forceinline__ uint32_t f2tf32(float f) {
    uint32_t u;
    asm("cvt.rna.tf32.f32 %0, %1;" : "=r"(u) : "f"(f));
    return u;
}

__device__ __forceinline__ void mma_tf32(
    float* c, uint32_t a0, uint32_t a1, uint32_t a2, uint32_t a3,
    uint32_t b0, uint32_t b1)
{
    asm volatile(
        "mma.sync.aligned.m16n8k8.row.col.f32.tf32.tf32.f32 "
        "{%0,%1,%2,%3}, {%4,%5,%6,%7}, {%8,%9}, {%0,%1,%2,%3};"
        : "+f"(c[0]), "+f"(c[1]), "+f"(c[2]), "+f"(c[3])
        : "r"(a0), "r"(a1), "r"(a2), "r"(a3), "r"(b0), "r"(b1));
}

__device__ __forceinline__ uint32_t smem_u32(const void* p) {
    uint32_t a;
    asm("{ .reg .u64 t; cvta.to.shared.u64 t, %1; cvt.u32.u64 %0, t; }"
        : "=r"(a) : "l"(p));
    return a;
}

#define LDSM4(r0, r1, r2, r3, addr) \
    asm volatile("ldmatrix.sync.aligned.m8n8.x4.shared.b16 {%0,%1,%2,%3}, [%4];" \
                 : "=r"(r0), "=r"(r1), "=r"(r2), "=r"(r3) : "r"(addr))

#define CP_ASYNC16(dst_u32, src) \
    asm volatile("cp.async.cg.shared.global [%0], [%1], 16;" \
                 :: "r"(dst_u32), "l"(src) : "memory")
#define CP_COMMIT() asm volatile("cp.async.commit_group;" ::: "memory")
#define CP_WAIT2()  asm volatile("cp.async.wait_group 2;" ::: "memory")

// ============================================================================
// Round fp32 -> tf32 (RNA), stored as fp32 bits.
// ============================================================================
__global__ void round_tf32(const float* __restrict__ in, float* __restrict__ out,
                           int n)
{
    int i = (blockIdx.x * blockDim.x + threadIdx.x) * 4;
    if (i >= n) return;
    float4 v = *(const float4*)(in + i);
    v.x = __uint_as_float(f2tf32(v.x));
    v.y = __uint_as_float(f2tf32(v.y));
    v.z = __uint_as_float(f2tf32(v.z));
    v.w = __uint_as_float(f2tf32(v.w));
    *(float4*)(out + i) = v;
}

// ============================================================================
// cp.async 4-stage tf32 GEMM with ldmatrix fragment loads.
// C[M,N] = A[M,K]*Bw[N,K]^T, K=1024. Inputs pre-rounded to tf32.
// CTA 128x128, 8 warps, warp 64x32, K-chunk 16.
// smem per stage: A[128][20] + B[128][20] floats (stride 80B -> the 8 LDSM
// row addresses land in distinct 16B slots: conflict-free).
// tf32 trick: one 8x8-b16 ldmatrix tile == an 8row x 4col tf32 block, so
// LDSM.x4 with address groups (r+0,k0)(r+8,k0)(r+0,k0+4)(r+8,k0+4) returns
// (a0,a1,a2,a3) of the m16k8 A-frag directly; B uses 2 n-blocks per LDSM.x4.
// MODE 0: scatter fp32 into g_q/g_k/g_v. MODE 1: row-major C.
// ============================================================================
#define GP        20
#define SSTRIDE   (2*128*GP)           // floats per stage = 5120
#define NSTAGE    4
#define GEMM_SMEM (NSTAGE*SSTRIDE*4)   // 81920 B
#define NCH       (Dv/16)              // 64

template<int MODE>
__global__ __launch_bounds__(256, 2)
void gemm_cp(const float* __restrict__ A, const float* __restrict__ Bw,
             float* __restrict__ C)
{
    extern __shared__ float smf[];
    const uint32_t sb32 = smem_u32(smf);

    const int tid  = threadIdx.x;
    const int wid  = tid >> 5, lane = tid & 31;
    const int gid  = lane >> 2, tg = lane & 3;
    const int wm   = (wid >> 2) * 64;
    const int wn   = (wid & 3) * 32;
    const int m0   = blockIdx.y * 128, n0 = blockIdx.x * 128;

    // cp.async assignment: row r0 = tid>>2, 16B chunk c4 = (tid&3)*4
    const int r0 = tid >> 2, c4 = (tid & 3) * 4;
    const float* gA0 = A  + (size_t)(m0 + r0) * Dv + c4;
    const float* gA1 = gA0 + (size_t)64 * Dv;
    const float* gB0 = Bw + (size_t)(n0 + r0) * Dv + c4;
    const float* gB1 = gB0 + (size_t)64 * Dv;
    const uint32_t dA0 = sb32 + (r0*GP + c4) * 4;
    const uint32_t dA1 = dA0 + 64*GP*4;
    const uint32_t dB0 = dA0 + 2560*4;
    const uint32_t dB1 = dB0 + 64*GP*4;

    // ldmatrix addresses (stage-0 base)
    const int lrow = lane & 7, lsel = lane >> 3;   // address group
    uint32_t a_addr[4], b_addr[2];
    {
        const int arow = wm + ((lsel & 1) ? 8 : 0) + lrow;
        const int acol = (lsel >> 1) * 4;
        #pragma unroll
        for (int mi = 0; mi < 4; mi++)
            a_addr[mi] = sb32 + ((arow + mi*16)*GP + acol) * 4;
        const int bcol = (lsel & 1) * 4;
        #pragma unroll
        for (int p = 0; p < 2; p++) {
            const int brow = wn + (p*2 + (lsel >> 1))*8 + lrow;
            b_addr[p] = sb32 + 2560*4 + (brow*GP + bcol) * 4;
        }
    }

    float acc[4][4][4];
    #pragma unroll
    for (int i = 0; i < 4; i++)
        #pragma unroll
        for (int j = 0; j < 4; j++)
            #pragma unroll
            for (int r = 0; r < 4; r++) acc[i][j][r] = 0.f;

    // prologue: stages 0..2
    #pragma unroll
    for (int p = 0; p < NSTAGE-1; p++) {
        const uint32_t so = p * SSTRIDE * 4;
        const int ko = p * 16;
        CP_ASYNC16(dA0 + so, gA0 + ko);
        CP_ASYNC16(dA1 + so, gA1 + ko);
        CP_ASYNC16(dB0 + so, gB0 + ko);
        CP_ASYNC16(dB1 + so, gB1 + ko);
        CP_COMMIT();
    }

    int st = 0;
    for (int ch = 0; ch < NCH; ++ch) {
        CP_WAIT2();
        __syncthreads();

        // prefetch ch+3 into stage (st+3)&3 (freed at the sync above)
        if (ch + NSTAGE-1 < NCH) {
            const uint32_t so = ((st + NSTAGE-1) & (NSTAGE-1)) * SSTRIDE * 4;
            const int ko = (ch + NSTAGE-1) * 16;
            CP_ASYNC16(dA0 + so, gA0 + ko);
            CP_ASYNC16(dA1 + so, gA1 + ko);
            CP_ASYNC16(dB0 + so, gB0 + ko);
            CP_ASYNC16(dB1 + so, gB1 + ko);
        }
        CP_COMMIT();

        const uint32_t stoff = st * SSTRIDE * 4;
        #pragma unroll
        for (int ks = 0; ks < 2; ks++) {
            const uint32_t ko = stoff + ks * 32;   // k0*4 bytes
            uint32_t af[4][4], bf[4][2];
            #pragma unroll
            for (int mi = 0; mi < 4; mi++)
                LDSM4(af[mi][0], af[mi][1], af[mi][2], af[mi][3], a_addr[mi] + ko);
            #pragma unroll
            for (int p = 0; p < 2; p++)
                LDSM4(bf[2*p][0], bf[2*p][1], bf[2*p+1][0], bf[2*p+1][1],
                      b_addr[p] + ko);
            #pragma unroll
            for (int mi = 0; mi < 4; mi++)
                #pragma unroll
                for (int ni = 0; ni < 4; ni++)
                    mma_tf32(acc[mi][ni],
                             af[mi][0], af[mi][1], af[mi][2], af[mi][3],
                             bf[ni][0], bf[ni][1]);
        }
        st = (st + 1) & (NSTAGE - 1);
    }

    // ---- epilogue ----
    #pragma unroll
    for (int mi = 0; mi < 4; mi++) {
        #pragma unroll
        for (int half = 0; half < 2; half++) {
            const int m = m0 + wm + mi * 16 + gid + half * 8;
            const int bb = m >> 11, trow = m & (Tv - 1);
            #pragma unroll
            for (int ni = 0; ni < 4; ni++) {
                const int n = n0 + wn + ni * 8 + tg * 2;
                float2 val;
                val.x = acc[mi][ni][half * 2 + 0];
                val.y = acc[mi][ni][half * 2 + 1];
                if (MODE == 0) {
                    const int wh = n >> 10;
                    const int d  = n & (Dv - 1);
                    const int h  = d >> 6, dd = d & 63;
                    float* dst = ((wh == 0) ? g_q : (wh == 1) ? g_k : g_v)
                               + ((size_t)(bb * Hv + h) * Tv + trow) * DHv + dd;
                    *(float2*)dst = val;
                } else {
                    *(float2*)(C + (size_t)m * Dv + n) = val;
                }
            }
        }
    }
}

// ============================================================================
// RoPE on g_q and g_k in place.
// ============================================================================
__global__ void rope_kernel(const float* __restrict__ cosT,
                            const float* __restrict__ sinT)
{
    int gid = blockIdx.x * blockDim.x + threadIdx.x;
    if (gid >= Bv*Hv*Tv*HALFv) return;
    int i   = gid & (HALFv - 1);
    int row = gid >> 5;
    int t   = row & (Tv - 1);
    float c = cosT[t*HALFv + i];
    float s = sinT[t*HALFv + i];

    float* qp = g_q + (size_t)row * DHv;
    float q1 = qp[i], q2 = qp[i + HALFv];
    qp[i]          = q1*c - q2*s;
    qp[i + HALFv]  = q1*s + q2*c;

    float* kp = g_k + (size_t)row * DHv;
    float k1 = kp[i], k2 = kp[i + HALFv];
    kp[i]          = k1*c - k2*s;
    kp[i + HALFv]  = k1*s + k2*c;
}

// ============================================================================
// Pack K (tf32 hi) and V into mma b-fragment order (post-RoPE).
// ============================================================================
__global__ __launch_bounds__(256)
void pack_kv()
{
    const int kb = blockIdx.x, bh = blockIdx.y;
    const size_t base = ((size_t)(bh * NKB + kb)) * 64 * 32;
    const size_t rowbase = (size_t)bh * Tv + kb * 64;

    #pragma unroll
    for (int i = 0; i < 8; i++) {
        int e = threadIdx.x + i * 256;      // 0..2047
        int lane = e & 31, fi = e >> 5;
        int gid = lane >> 2, tg = lane & 3;
        int ks = fi >> 3, nf = fi & 7;

        const float* kp = g_k + (rowbase + nf*8 + gid) * DHv + ks*8 + tg;
        g_kpk[base + (size_t)fi*32 + lane] =
            make_uint2(f2tf32(kp[0]), f2tf32(kp[4]));

        const float* vp = g_v + (rowbase + ks*8 + tg) * DHv + nf*8 + gid;
        g_vpk[base + (size_t)fi*32 + lane] =
            make_uint2(f2tf32(vp[0]), f2tf32(vp[4*DHv]));
    }
}

// ============================================================================
// Flash attention: barrier-free mainloop, fragments LDG'd from g_kpk/g_vpk.
// QK^T 2-term split (q_hi*k + q_lo*k), PV tf32. Diagonal kept in denom,
// zeroed in P. Epilogue rounds output to tf32 for the proj GEMM.
// ============================================================================
#define ATTN_SMEM (3*32768)

__global__ __launch_bounds__(256, 2)
void attn_mma()
{
    extern __shared__ char sm[];
    uint4*  Qhip = (uint4*)sm;
    uint4*  Qlop = (uint4*)(sm + 32768);
    float4* Ppk  = (float4*)(sm + 65536);

    const int qb = (int)gridDim.x - 1 - (int)blockIdx.x;  // heavy tiles first
    const int bh = blockIdx.y;
    const int tid = threadIdx.x;
    const int w = tid >> 5, lane = tid & 31;
    const int gid = lane >> 2, tg = lane & 3;

    const int rowA = qb*128 + 16*w + gid;
    const int rowB = rowA + 8;

    // ---- Q fragments (scaled, hi/lo) -> warp-private smem ----
    {
        const float* qA = g_q + ((size_t)bh*Tv + rowA) * DHv + tg;
        const float* qB = qA + 8 * DHv;
        #pragma unroll
        for (int ks = 0; ks < 8; ks++) {
            float q0 = qA[ks*8    ] * 0.125f;
            float q1 = qB[ks*8    ] * 0.125f;
            float q2 = qA[ks*8 + 4] * 0.125f;
            float q3 = qB[ks*8 + 4] * 0.125f;
            uint32_t h0 = f2tf32(q0), h1 = f2tf32(q1);
            uint32_t h2 = f2tf32(q2), h3 = f2tf32(q3);
            Qhip[(w*8 + ks)*32 + lane] = make_uint4(h0, h1, h2, h3);
            Qlop[(w*8 + ks)*32 + lane] =
                make_uint4(f2tf32(q0 - __uint_as_float(h0)),
                           f2tf32(q1 - __uint_as_float(h1)),
                           f2tf32(q2 - __uint_as_float(h2)),
                           f2tf32(q3 - __uint_as_float(h3)));
        }
    }
    __syncwarp();

    float O[8][4];
    #pragma unroll
    for (int d = 0; d < 8; d++)
        #pragma unroll
        for (int r = 0; r < 4; r++) O[d][r] = 0.f;
    float m0 = -1e30f, m1 = -1e30f, l0 = 0.f, l1 = 0.f;

    const uint2* kpk = g_kpk + (size_t)bh * NKB * 2048 + lane;
    const uint2* vpk = g_vpk + (size_t)bh * NKB * 2048 + lane;

    const int niter = 2 * (qb + 1);
    for (int j = 0; j < niter; j++) {
        const int k0g = j * 64;
        const uint2* kt = kpk + (size_t)j * 2048;
        const uint2* vt = vpk + (size_t)j * 2048;

        // ---- S = Q K^T (2-term split) ----
        float S[8][4];
        #pragma unroll
        for (int nf = 0; nf < 8; nf++)
            #pragma unroll
            for (int r = 0; r < 4; r++) S[nf][r] = 0.f;
        #pragma unroll
        for (int ks = 0; ks < 8; ks++) {
            uint4 qh = Qhip[(w*8 + ks)*32 + lane];
            uint4 ql = Qlop[(w*8 + ks)*32 + lane];
            #pragma unroll
            for (int nf = 0; nf < 8; nf++) {
                uint2 kf = kt[(ks*8 + nf)*32];
                mma_tf32(S[nf], qh.x, qh.y, qh.z, qh.w, kf.x, kf.y);
                mma_tf32(S[nf], ql.x, ql.y, ql.z, ql.w, kf.x, kf.y);
            }
        }

        // ---- mask + online softmax ----
        float mxA = -1e30f, mxB = -1e30f;
        #pragma unroll
        for (int nf = 0; nf < 8; nf++) {
            const int cA = k0g + nf*8 + 2*tg, cB = cA + 1;
            if (cA > rowA) S[nf][0] = -1e30f;
            if (cB > rowA) S[nf][1] = -1e30f;
            if (cA > rowB) S[nf][2] = -1e30f;
            if (cB > rowB) S[nf][3] = -1e30f;
            mxA = fmaxf(mxA, fmaxf(S[nf][0], S[nf][1]));
            mxB = fmaxf(mxB, fmaxf(S[nf][2], S[nf][3]));
        }
        mxA = fmaxf(mxA, __shfl_xor_sync(0xffffffffu, mxA, 1));
        mxA = fmaxf(mxA, __shfl_xor_sync(0xffffffffu, mxA, 2));
        mxB = fmaxf(mxB, __shfl_xor_sync(0xffffffffu, mxB, 1));
        mxB = fmaxf(mxB, __shfl_xor_sync(0xffffffffu, mxB, 2));
        const float mnA = fmaxf(m0, mxA), mnB = fmaxf(m1, mxB);
        const float corrA = __expf(m0 - mnA), corrB = __expf(m1 - mnB);

        float sA = 0.f, sB = 0.f;
        #pragma unroll
        for (int nf = 0; nf < 8; nf++) {
            const int cA = k0g + nf*8 + 2*tg, cB = cA + 1;
            float e0 = __expf(S[nf][0] - mnA);
            float e1 = __expf(S[nf][1] - mnA);
            float e2 = __expf(S[nf][2] - mnB);
            float e3 = __expf(S[nf][3] - mnB);
            sA += e0 + e1; sB += e2 + e3;
            if (cA == rowA) e0 = 0.f;
            if (cB == rowA) e1 = 0.f;
            if (cA == rowB) e2 = 0.f;
            if (cB == rowB) e3 = 0.f;
            {
                const int c0p = 2*tg;
                char* b = (char*)&Ppk[(w*8 + nf)*32 + 4*gid + (c0p & 3)];
                *(uint2*)(b + ((c0p < 4) ? 0 : 8)) = make_uint2(f2tf32(e0), f2tf32(e2));
            }
            {
                const int c1p = 2*tg + 1;
                char* b = (char*)&Ppk[(w*8 + nf)*32 + 4*gid + (c1p & 3)];
                *(uint2*)(b + ((c1p < 4) ? 0 : 8)) = make_uint2(f2tf32(e1), f2tf32(e3));
            }
        }
        sA += __shfl_xor_sync(0xffffffffu, sA, 1);
        sA += __shfl_xor_sync(0xffffffffu, sA, 2);
        sB += __shfl_xor_sync(0xffffffffu, sB, 1);
        sB += __shfl_xor_sync(0xffffffffu, sB, 2);
        l0 = l0 * corrA + sA;  m0 = mnA;
        l1 = l1 * corrB + sB;  m1 = mnB;
        #pragma unroll
        for (int d = 0; d < 8; d++) {
            O[d][0] *= corrA; O[d][1] *= corrA;
            O[d][2] *= corrB; O[d][3] *= corrB;
        }
        __syncwarp();

        // ---- O += P V (tf32) ----
        #pragma unroll
        for (int cs = 0; cs < 8; cs++) {
            uint4 a = *(const uint4*)&Ppk[(w*8 + cs)*32 + lane];
            #pragma unroll
            for (int df = 0; df < 8; df++) {
                uint2 b = vt[(cs*8 + df)*32];
                mma_tf32(O[df], a.x, a.y, a.z, a.w, b.x, b.y);
            }
        }
        __syncwarp();
    }

    // ---- epilogue (round to tf32 for the proj GEMM) ----
    const int bb = bh >> 4, h = bh & 15;
    const float inv0 = 1.f / l0, inv1 = 1.f / l1;
    #pragma unroll
    for (int df = 0; df < 8; df++) {
        const int col = h*64 + df*8 + 2*tg;
        float2 vA, vB;
        vA.x = __uint_as_float(f2tf32(O[df][0] * inv0));
        vA.y = __uint_as_float(f2tf32(O[df][1] * inv0));
        vB.x = __uint_as_float(f2tf32(O[df][2] * inv1));
        vB.y = __uint_as_float(f2tf32(O[df][3] * inv1));
        *(float2*)&g_attn[((size_t)bb*Tv + rowA) * Dv + col] = vA;
        *(float2*)&g_attn[((size_t)bb*Tv + rowB) * Dv + col] = vB;
    }
}

// ============================================================================
extern "C" void kernel_launch(void* const* d_in, const int* in_sizes, int n_in,
                              void* d_out, int out_size)
{
    const float* x     = (const float*)d_in[0];
    const float* cosT  = (const float*)d_in[1];
    const float* sinT  = (const float*)d_in[2];
    const float* Wqkv  = (const float*)d_in[3];
    const float* Wproj = (const float*)d_in[4];

    float *attn_ptr, *xr_ptr, *wqkvr_ptr, *wprojr_ptr;
    cudaGetSymbolAddress((void**)&attn_ptr,   g_attn);
    cudaGetSymbolAddress((void**)&xr_ptr,     g_xr);
    cudaGetSymbolAddress((void**)&wqkvr_ptr,  g_wqkvr);
    cudaGetSymbolAddress((void**)&wprojr_ptr, g_wprojr);

    cudaFuncSetAttribute(attn_mma, cudaFuncAttributeMaxDynamicSharedMemorySize, ATTN_SMEM);
    cudaFuncSetAttribute(gemm_cp<0>, cudaFuncAttributeMaxDynamicSharedMemorySize, GEMM_SMEM);
    cudaFuncSetAttribute(gemm_cp<1>, cudaFuncAttributeMaxDynamicSharedMemorySize, GEMM_SMEM);

    // 0) pre-round GEMM inputs to tf32
    round_tf32<<<MROWS*Dv/1024, 256>>>(x, xr_ptr, MROWS*Dv);
    round_tf32<<<NQKV*Dv/1024, 256>>>(Wqkv, wqkvr_ptr, NQKV*Dv);
    round_tf32<<<Dv*Dv/1024, 256>>>(Wproj, wprojr_ptr, Dv*Dv);

    // 1) QKV projection (cp.async + ldmatrix tf32 mma), scattered into [b,h,t,dh]
    gemm_cp<0><<<dim3(NQKV/128, MROWS/128), 256, GEMM_SMEM>>>(xr_ptr, wqkvr_ptr, nullptr);
    // 2) RoPE on q,k
    rope_kernel<<<(Bv*Hv*Tv*HALFv + 255)/256, 256>>>(cosT, sinT);
    // 3) pack K/V into mma fragment order
    pack_kv<<<dim3(NKB, Bv*Hv), 256>>>();
    // 4) causal attention on tensor cores (barrier-free mainloop)
    attn_mma<<<dim3(Tv/128, Bv*Hv), 256, ATTN_SMEM>>>();
    // 5) output projection -> d_out
    gemm_cp<1><<<dim3(Dv/128, MROWS/128), 256, GEMM_SMEM>>>(attn_ptr, wprojr_ptr, (float*)d_out);
}

// round 9
// speedup vs baseline: 1.9032x; 1.0535x over previous
#include <cuda_runtime.h>
#include <math.h>
#include <stdint.h>

#define Bv    4
#define Tv    2048
#define Dv    1024
#define Hv    16
#define DHv   64
#define HALFv 32
#define MROWS (Bv*Tv)      // 8192
#define NQKV  (3*Dv)       // 3072
#define NKB   (Tv/64)      // 32 key tiles per bh

// ---- scratch (device globals) ----
__device__ float g_q[Bv*Hv*Tv*DHv];     // [b,h,t,dh] fp32 (RoPE'd)
__device__ float g_k[Bv*Hv*Tv*DHv];     // [b,h,t,dh] fp32 (pre-RoPE; rope fused into pack)
__device__ float g_v[Bv*Hv*Tv*DHv];
__device__ float g_attn[MROWS*Dv];      // [b,t,d], tf32-rounded by attn epilogue
__device__ float g_xr[MROWS*Dv];        // tf32-rounded x
__device__ float g_wqkvr[NQKV*Dv];      // tf32-rounded W_qkv
__device__ float g_wprojr[Dv*Dv];       // tf32-rounded W_proj
// packed fragments, pairwise: [bh][kb][pi(32)][lane(32)] of uint4
//   K: pi = ks*4 + nf2 -> (kh0,kh1) of nf=2*nf2 and nf=2*nf2+1
//   V: pi = cs*4 + df2 -> (v0,v1) of df=2*df2 and df=2*df2+1
__device__ uint2 g_kpk[64*NKB*64*32];   // viewed as uint4[...*32*32]
__device__ uint2 g_vpk[64*NKB*64*32];

__device__ __forceinline__ uint32_t f2tf32(float f) {
    uint32_t u;
    asm("cvt.rna.tf32.f32 %0, %1;" : "=r"(u) : "f"(f));
    return u;
}

__device__ __forceinline__ void mma_tf32(
    float* c, uint32_t a0, uint32_t a1, uint32_t a2, uint32_t a3,
    uint32_t b0, uint32_t b1)
{
    asm volatile(
        "mma.sync.aligned.m16n8k8.row.col.f32.tf32.tf32.f32 "
        "{%0,%1,%2,%3}, {%4,%5,%6,%7}, {%8,%9}, {%0,%1,%2,%3};"
        : "+f"(c[0]), "+f"(c[1]), "+f"(c[2]), "+f"(c[3])
        : "r"(a0), "r"(a1), "r"(a2), "r"(a3), "r"(b0), "r"(b1));
}

__device__ __forceinline__ uint32_t smem_u32(const void* p) {
    uint32_t a;
    asm("{ .reg .u64 t; cvta.to.shared.u64 t, %1; cvt.u32.u64 %0, t; }"
        : "=r"(a) : "l"(p));
    return a;
}

#define LDSM4(r0, r1, r2, r3, addr) \
    asm volatile("ldmatrix.sync.aligned.m8n8.x4.shared.b16 {%0,%1,%2,%3}, [%4];" \
                 : "=r"(r0), "=r"(r1), "=r"(r2), "=r"(r3) : "r"(addr))

#define CP_ASYNC16(dst_u32, src) \
    asm volatile("cp.async.cg.shared.global [%0], [%1], 16;" \
                 :: "r"(dst_u32), "l"(src) : "memory")
#define CP_COMMIT() asm volatile("cp.async.commit_group;" ::: "memory")
#define CP_WAIT2()  asm volatile("cp.async.wait_group 2;" ::: "memory")

// ============================================================================
// Round fp32 -> tf32 (RNA), stored as fp32 bits.
// ============================================================================
__global__ void round_tf32(const float* __restrict__ in, float* __restrict__ out,
                           int n)
{
    int i = (blockIdx.x * blockDim.x + threadIdx.x) * 4;
    if (i >= n) return;
    float4 v = *(const float4*)(in + i);
    v.x = __uint_as_float(f2tf32(v.x));
    v.y = __uint_as_float(f2tf32(v.y));
    v.z = __uint_as_float(f2tf32(v.z));
    v.w = __uint_as_float(f2tf32(v.w));
    *(float4*)(out + i) = v;
}

// ============================================================================
// cp.async 4-stage tf32 GEMM with ldmatrix fragment loads (unchanged R8).
// ============================================================================
#define GP        20
#define SSTRIDE   (2*128*GP)           // floats per stage = 5120
#define NSTAGE    4
#define GEMM_SMEM (NSTAGE*SSTRIDE*4)   // 81920 B
#define NCH       (Dv/16)              // 64

template<int MODE>
__global__ __launch_bounds__(256, 2)
void gemm_cp(const float* __restrict__ A, const float* __restrict__ Bw,
             float* __restrict__ C)
{
    extern __shared__ float smf[];
    const uint32_t sb32 = smem_u32(smf);

    const int tid  = threadIdx.x;
    const int wid  = tid >> 5, lane = tid & 31;
    const int gid  = lane >> 2, tg = lane & 3;
    const int wm   = (wid >> 2) * 64;
    const int wn   = (wid & 3) * 32;
    const int m0   = blockIdx.y * 128, n0 = blockIdx.x * 128;

    const int r0 = tid >> 2, c4 = (tid & 3) * 4;
    const float* gA0 = A  + (size_t)(m0 + r0) * Dv + c4;
    const float* gA1 = gA0 + (size_t)64 * Dv;
    const float* gB0 = Bw + (size_t)(n0 + r0) * Dv + c4;
    const float* gB1 = gB0 + (size_t)64 * Dv;
    const uint32_t dA0 = sb32 + (r0*GP + c4) * 4;
    const uint32_t dA1 = dA0 + 64*GP*4;
    const uint32_t dB0 = dA0 + 2560*4;
    const uint32_t dB1 = dB0 + 64*GP*4;

    const int lrow = lane & 7, lsel = lane >> 3;
    uint32_t a_addr[4], b_addr[2];
    {
        const int arow = wm + ((lsel & 1) ? 8 : 0) + lrow;
        const int acol = (lsel >> 1) * 4;
        #pragma unroll
        for (int mi = 0; mi < 4; mi++)
            a_addr[mi] = sb32 + ((arow + mi*16)*GP + acol) * 4;
        const int bcol = (lsel & 1) * 4;
        #pragma unroll
        for (int p = 0; p < 2; p++) {
            const int brow = wn + (p*2 + (lsel >> 1))*8 + lrow;
            b_addr[p] = sb32 + 2560*4 + (brow*GP + bcol) * 4;
        }
    }

    float acc[4][4][4];
    #pragma unroll
    for (int i = 0; i < 4; i++)
        #pragma unroll
        for (int j = 0; j < 4; j++)
            #pragma unroll
            for (int r = 0; r < 4; r++) acc[i][j][r] = 0.f;

    #pragma unroll
    for (int p = 0; p < NSTAGE-1; p++) {
        const uint32_t so = p * SSTRIDE * 4;
        const int ko = p * 16;
        CP_ASYNC16(dA0 + so, gA0 + ko);
        CP_ASYNC16(dA1 + so, gA1 + ko);
        CP_ASYNC16(dB0 + so, gB0 + ko);
        CP_ASYNC16(dB1 + so, gB1 + ko);
        CP_COMMIT();
    }

    int st = 0;
    for (int ch = 0; ch < NCH; ++ch) {
        CP_WAIT2();
        __syncthreads();

        if (ch + NSTAGE-1 < NCH) {
            const uint32_t so = ((st + NSTAGE-1) & (NSTAGE-1)) * SSTRIDE * 4;
            const int ko = (ch + NSTAGE-1) * 16;
            CP_ASYNC16(dA0 + so, gA0 + ko);
            CP_ASYNC16(dA1 + so, gA1 + ko);
            CP_ASYNC16(dB0 + so, gB0 + ko);
            CP_ASYNC16(dB1 + so, gB1 + ko);
        }
        CP_COMMIT();

        const uint32_t stoff = st * SSTRIDE * 4;
        #pragma unroll
        for (int ks = 0; ks < 2; ks++) {
            const uint32_t ko = stoff + ks * 32;
            uint32_t af[4][4], bf[4][2];
            #pragma unroll
            for (int mi = 0; mi < 4; mi++)
                LDSM4(af[mi][0], af[mi][1], af[mi][2], af[mi][3], a_addr[mi] + ko);
            #pragma unroll
            for (int p = 0; p < 2; p++)
                LDSM4(bf[2*p][0], bf[2*p][1], bf[2*p+1][0], bf[2*p+1][1],
                      b_addr[p] + ko);
            #pragma unroll
            for (int mi = 0; mi < 4; mi++)
                #pragma unroll
                for (int ni = 0; ni < 4; ni++)
                    mma_tf32(acc[mi][ni],
                             af[mi][0], af[mi][1], af[mi][2], af[mi][3],
                             bf[ni][0], bf[ni][1]);
        }
        st = (st + 1) & (NSTAGE - 1);
    }

    #pragma unroll
    for (int mi = 0; mi < 4; mi++) {
        #pragma unroll
        for (int half = 0; half < 2; half++) {
            const int m = m0 + wm + mi * 16 + gid + half * 8;
            const int bb = m >> 11, trow = m & (Tv - 1);
            #pragma unroll
            for (int ni = 0; ni < 4; ni++) {
                const int n = n0 + wn + ni * 8 + tg * 2;
                float2 val;
                val.x = acc[mi][ni][half * 2 + 0];
                val.y = acc[mi][ni][half * 2 + 1];
                if (MODE == 0) {
                    const int wh = n >> 10;
                    const int d  = n & (Dv - 1);
                    const int h  = d >> 6, dd = d & 63;
                    float* dst = ((wh == 0) ? g_q : (wh == 1) ? g_k : g_v)
                               + ((size_t)(bb * Hv + h) * Tv + trow) * DHv + dd;
                    *(float2*)dst = val;
                } else {
                    *(float2*)(C + (size_t)m * Dv + n) = val;
                }
            }
        }
    }
}

// ============================================================================
// RoPE on g_q only (K rope is fused into pack_kv).
// ============================================================================
__global__ void rope_q(const float* __restrict__ cosT,
                       const float* __restrict__ sinT)
{
    int gid = blockIdx.x * blockDim.x + threadIdx.x;
    if (gid >= Bv*Hv*Tv*HALFv) return;
    int i   = gid & (HALFv - 1);
    int row = gid >> 5;
    int t   = row & (Tv - 1);
    float c = cosT[t*HALFv + i];
    float s = sinT[t*HALFv + i];

    float* qp = g_q + (size_t)row * DHv;
    float q1 = qp[i], q2 = qp[i + HALFv];
    qp[i]          = q1*c - q2*s;
    qp[i + HALFv]  = q1*s + q2*c;
}

// ============================================================================
// Pack K (RoPE fused, tf32) and V into pairwise mma b-fragment order.
// uint4 slot pi=ks*4+nf2: (x,y)=frag nf=2*nf2, (z,w)=frag nf=2*nf2+1.
// Stored via uint2 halves: idx = (pi*32 + lane)*2 + (nf&1).
// ============================================================================
__global__ __launch_bounds__(256)
void pack_kv(const float* __restrict__ cosT, const float* __restrict__ sinT)
{
    const int kb = blockIdx.x, bh = blockIdx.y;
    const size_t base = ((size_t)(bh * NKB + kb)) * 2048;   // uint2 units
    const size_t rowbase = (size_t)bh * Tv + kb * 64;

    #pragma unroll
    for (int i = 0; i < 8; i++) {
        int e = threadIdx.x + i * 256;      // 0..2047
        int lane = e & 31, fi = e >> 5;
        int gid = lane >> 2, tg = lane & 3;
        int ks = fi >> 3, nf = fi & 7;

        // ---- K fragment with fused RoPE ----
        {
            const int trow = kb*64 + nf*8 + gid;       // position in sequence
            const float* kp = g_k + (rowbase + nf*8 + gid) * DHv;
            const int dd = ks*8 + tg;                  // dd and dd+4, same half
            float r0, r1;
            if (dd < HALFv) {
                float c0 = cosT[trow*HALFv + dd],     s0 = sinT[trow*HALFv + dd];
                float c1 = cosT[trow*HALFv + dd + 4], s1 = sinT[trow*HALFv + dd + 4];
                r0 = kp[dd]     * c0 - kp[dd + HALFv]     * s0;
                r1 = kp[dd + 4] * c1 - kp[dd + 4 + HALFv] * s1;
            } else {
                const int i0 = dd - HALFv;
                float c0 = cosT[trow*HALFv + i0],     s0 = sinT[trow*HALFv + i0];
                float c1 = cosT[trow*HALFv + i0 + 4], s1 = sinT[trow*HALFv + i0 + 4];
                r0 = kp[i0]     * s0 + kp[dd]     * c0;
                r1 = kp[i0 + 4] * s1 + kp[dd + 4] * c1;
            }
            const int pi = ks*4 + (nf >> 1);
            g_kpk[base + ((size_t)pi*32 + lane)*2 + (nf & 1)] =
                make_uint2(f2tf32(r0), f2tf32(r1));
        }

        // ---- V fragment (cs = ks, df = nf) ----
        {
            const float* vp = g_v + (rowbase + ks*8 + tg) * DHv + nf*8 + gid;
            const int pi = ks*4 + (nf >> 1);
            g_vpk[base + ((size_t)pi*32 + lane)*2 + (nf & 1)] =
                make_uint2(f2tf32(vp[0]), f2tf32(vp[4*DHv]));
        }
    }
}

// ============================================================================
// Flash attention: barrier-free mainloop, pairwise-packed fragments (LDG.128).
// QK^T 2-term split, PV tf32. Diagonal kept in denom, zeroed in P.
// ============================================================================
#define ATTN_SMEM (3*32768)

__global__ __launch_bounds__(256, 2)
void attn_mma()
{
    extern __shared__ char sm[];
    uint4*  Qhip = (uint4*)sm;
    uint4*  Qlop = (uint4*)(sm + 32768);
    float4* Ppk  = (float4*)(sm + 65536);

    const int qb = (int)gridDim.x - 1 - (int)blockIdx.x;  // heavy tiles first
    const int bh = blockIdx.y;
    const int tid = threadIdx.x;
    const int w = tid >> 5, lane = tid & 31;
    const int gid = lane >> 2, tg = lane & 3;

    const int rowA = qb*128 + 16*w + gid;
    const int rowB = rowA + 8;

    // ---- Q fragments (scaled, hi/lo) -> warp-private smem ----
    {
        const float* qA = g_q + ((size_t)bh*Tv + rowA) * DHv + tg;
        const float* qB = qA + 8 * DHv;
        #pragma unroll
        for (int ks = 0; ks < 8; ks++) {
            float q0 = qA[ks*8    ] * 0.125f;
            float q1 = qB[ks*8    ] * 0.125f;
            float q2 = qA[ks*8 + 4] * 0.125f;
            float q3 = qB[ks*8 + 4] * 0.125f;
            uint32_t h0 = f2tf32(q0), h1 = f2tf32(q1);
            uint32_t h2 = f2tf32(q2), h3 = f2tf32(q3);
            Qhip[(w*8 + ks)*32 + lane] = make_uint4(h0, h1, h2, h3);
            Qlop[(w*8 + ks)*32 + lane] =
                make_uint4(f2tf32(q0 - __uint_as_float(h0)),
                           f2tf32(q1 - __uint_as_float(h1)),
                           f2tf32(q2 - __uint_as_float(h2)),
                           f2tf32(q3 - __uint_as_float(h3)));
        }
    }
    __syncwarp();

    float O[8][4];
    #pragma unroll
    for (int d = 0; d < 8; d++)
        #pragma unroll
        for (int r = 0; r < 4; r++) O[d][r] = 0.f;
    float m0 = -1e30f, m1 = -1e30f, l0 = 0.f, l1 = 0.f;

    const uint4* kpk = (const uint4*)g_kpk + (size_t)bh * NKB * 1024 + lane;
    const uint4* vpk = (const uint4*)g_vpk + (size_t)bh * NKB * 1024 + lane;

    const int niter = 2 * (qb + 1);
    for (int j = 0; j < niter; j++) {
        const int k0g = j * 64;
        const uint4* kt = kpk + (size_t)j * 1024;
        const uint4* vt = vpk + (size_t)j * 1024;

        // ---- S = Q K^T (2-term split) ----
        float S[8][4];
        #pragma unroll
        for (int nf = 0; nf < 8; nf++)
            #pragma unroll
            for (int r = 0; r < 4; r++) S[nf][r] = 0.f;
        #pragma unroll
        for (int ks = 0; ks < 8; ks++) {
            uint4 qh = Qhip[(w*8 + ks)*32 + lane];
            uint4 ql = Qlop[(w*8 + ks)*32 + lane];
            #pragma unroll
            for (int nf2 = 0; nf2 < 4; nf2++) {
                uint4 kf = kt[(ks*4 + nf2)*32];
                mma_tf32(S[2*nf2    ], qh.x, qh.y, qh.z, qh.w, kf.x, kf.y);
                mma_tf32(S[2*nf2    ], ql.x, ql.y, ql.z, ql.w, kf.x, kf.y);
                mma_tf32(S[2*nf2 + 1], qh.x, qh.y, qh.z, qh.w, kf.z, kf.w);
                mma_tf32(S[2*nf2 + 1], ql.x, ql.y, ql.z, ql.w, kf.z, kf.w);
            }
        }

        // ---- mask + online softmax ----
        float mxA = -1e30f, mxB = -1e30f;
        #pragma unroll
        for (int nf = 0; nf < 8; nf++) {
            const int cA = k0g + nf*8 + 2*tg, cB = cA + 1;
            if (cA > rowA) S[nf][0] = -1e30f;
            if (cB > rowA) S[nf][1] = -1e30f;
            if (cA > rowB) S[nf][2] = -1e30f;
            if (cB > rowB) S[nf][3] = -1e30f;
            mxA = fmaxf(mxA, fmaxf(S[nf][0], S[nf][1]));
            mxB = fmaxf(mxB, fmaxf(S[nf][2], S[nf][3]));
        }
        mxA = fmaxf(mxA, __shfl_xor_sync(0xffffffffu, mxA, 1));
        mxA = fmaxf(mxA, __shfl_xor_sync(0xffffffffu, mxA, 2));
        mxB = fmaxf(mxB, __shfl_xor_sync(0xffffffffu, mxB, 1));
        mxB = fmaxf(mxB, __shfl_xor_sync(0xffffffffu, mxB, 2));
        const float mnA = fmaxf(m0, mxA), mnB = fmaxf(m1, mxB);
        const float corrA = __expf(m0 - mnA), corrB = __expf(m1 - mnB);

        float sA = 0.f, sB = 0.f;
        #pragma unroll
        for (int nf = 0; nf < 8; nf++) {
            const int cA = k0g + nf*8 + 2*tg, cB = cA + 1;
            float e0 = __expf(S[nf][0] - mnA);
            float e1 = __expf(S[nf][1] - mnA);
            float e2 = __expf(S[nf][2] - mnB);
            float e3 = __expf(S[nf][3] - mnB);
            sA += e0 + e1; sB += e2 + e3;
            if (cA == rowA) e0 = 0.f;
            if (cB == rowA) e1 = 0.f;
            if (cA == rowB) e2 = 0.f;
            if (cB == rowB) e3 = 0.f;
            {
                const int c0p = 2*tg;
                char* b = (char*)&Ppk[(w*8 + nf)*32 + 4*gid + (c0p & 3)];
                *(uint2*)(b + ((c0p < 4) ? 0 : 8)) = make_uint2(f2tf32(e0), f2tf32(e2));
            }
            {
                const int c1p = 2*tg + 1;
                char* b = (char*)&Ppk[(w*8 + nf)*32 + 4*gid + (c1p & 3)];
                *(uint2*)(b + ((c1p < 4) ? 0 : 8)) = make_uint2(f2tf32(e1), f2tf32(e3));
            }
        }
        sA += __shfl_xor_sync(0xffffffffu, sA, 1);
        sA += __shfl_xor_sync(0xffffffffu, sA, 2);
        sB += __shfl_xor_sync(0xffffffffu, sB, 1);
        sB += __shfl_xor_sync(0xffffffffu, sB, 2);
        l0 = l0 * corrA + sA;  m0 = mnA;
        l1 = l1 * corrB + sB;  m1 = mnB;
        #pragma unroll
        for (int d = 0; d < 8; d++) {
            O[d][0] *= corrA; O[d][1] *= corrA;
            O[d][2] *= corrB; O[d][3] *= corrB;
        }
        __syncwarp();

        // ---- O += P V (tf32) ----
        #pragma unroll
        for (int cs = 0; cs < 8; cs++) {
            uint4 a = *(const uint4*)&Ppk[(w*8 + cs)*32 + lane];
            #pragma unroll
            for (int df2 = 0; df2 < 4; df2++) {
                uint4 b = vt[(cs*4 + df2)*32];
                mma_tf32(O[2*df2    ], a.x, a.y, a.z, a.w, b.x, b.y);
                mma_tf32(O[2*df2 + 1], a.x, a.y, a.z, a.w, b.z, b.w);
            }
        }
        __syncwarp();
    }

    // ---- epilogue (round to tf32 for the proj GEMM) ----
    const int bb = bh >> 4, h = bh & 15;
    const float inv0 = 1.f / l0, inv1 = 1.f / l1;
    #pragma unroll
    for (int df = 0; df < 8; df++) {
        const int col = h*64 + df*8 + 2*tg;
        float2 vA, vB;
        vA.x = __uint_as_float(f2tf32(O[df][0] * inv0));
        vA.y = __uint_as_float(f2tf32(O[df][1] * inv0));
        vB.x = __uint_as_float(f2tf32(O[df][2] * inv1));
        vB.y = __uint_as_float(f2tf32(O[df][3] * inv1));
        *(float2*)&g_attn[((size_t)bb*Tv + rowA) * Dv + col] = vA;
        *(float2*)&g_attn[((size_t)bb*Tv + rowB) * Dv + col] = vB;
    }
}

// ============================================================================
extern "C" void kernel_launch(void* const* d_in, const int* in_sizes, int n_in,
                              void* d_out, int out_size)
{
    const float* x     = (const float*)d_in[0];
    const float* cosT  = (const float*)d_in[1];
    const float* sinT  = (const float*)d_in[2];
    const float* Wqkv  = (const float*)d_in[3];
    const float* Wproj = (const float*)d_in[4];

    float *attn_ptr, *xr_ptr, *wqkvr_ptr, *wprojr_ptr;
    cudaGetSymbolAddress((void**)&attn_ptr,   g_attn);
    cudaGetSymbolAddress((void**)&xr_ptr,     g_xr);
    cudaGetSymbolAddress((void**)&wqkvr_ptr,  g_wqkvr);
    cudaGetSymbolAddress((void**)&wprojr_ptr, g_wprojr);

    cudaFuncSetAttribute(attn_mma, cudaFuncAttributeMaxDynamicSharedMemorySize, ATTN_SMEM);
    cudaFuncSetAttribute(gemm_cp<0>, cudaFuncAttributeMaxDynamicSharedMemorySize, GEMM_SMEM);
    cudaFuncSetAttribute(gemm_cp<1>, cudaFuncAttributeMaxDynamicSharedMemorySize, GEMM_SMEM);

    // 0) pre-round GEMM inputs to tf32
    round_tf32<<<MROWS*Dv/1024, 256>>>(x, xr_ptr, MROWS*Dv);
    round_tf32<<<NQKV*Dv/1024, 256>>>(Wqkv, wqkvr_ptr, NQKV*Dv);
    round_tf32<<<Dv*Dv/1024, 256>>>(Wproj, wprojr_ptr, Dv*Dv);

    // 1) QKV projection, scattered into [b,h,t,dh]
    gemm_cp<0><<<dim3(NQKV/128, MROWS/128), 256, GEMM_SMEM>>>(xr_ptr, wqkvr_ptr, nullptr);
    // 2) RoPE on q (k rope fused into pack_kv)
    rope_q<<<(Bv*Hv*Tv*HALFv + 255)/256, 256>>>(cosT, sinT);
    // 3) pack K (rope fused) / V into pairwise fragment order
    pack_kv<<<dim3(NKB, Bv*Hv), 256>>>(cosT, sinT);
    // 4) causal attention on tensor cores (barrier-free mainloop)
    attn_mma<<<dim3(Tv/128, Bv*Hv), 256, ATTN_SMEM>>>();
    // 5) output projection -> d_out
    gemm_cp<1><<<dim3(Dv/128, MROWS/128), 256, GEMM_SMEM>>>(attn_ptr, wprojr_ptr, (float*)d_out);
}

// round 11
// speedup vs baseline: 1.9781x; 1.0393x over previous
#include <cuda_runtime.h>
#include <math.h>
#include <stdint.h>

#define Bv    4
#define Tv    2048
#define Dv    1024
#define Hv    16
#define DHv   64
#define HALFv 32
#define MROWS (Bv*Tv)      // 8192
#define NQKV  (3*Dv)       // 3072
#define NKB   (Tv/64)      // 32 key tiles per bh

// ---- scratch (device globals) ----
__device__ float g_q[Bv*Hv*Tv*DHv];     // [b,h,t,dh] fp32 (RoPE'd)
__device__ float g_k[Bv*Hv*Tv*DHv];     // [b,h,t,dh] fp32 (pre-RoPE; rope fused into pack)
__device__ float g_v[Bv*Hv*Tv*DHv];
__device__ float g_attn[MROWS*Dv];      // [b,t,d], tf32-rounded by attn epilogue
__device__ float g_xr[MROWS*Dv];        // tf32-rounded x
__device__ float g_wqkvr[NQKV*Dv];      // tf32-rounded W_qkv
__device__ float g_wprojr[Dv*Dv];       // tf32-rounded W_proj
// packed fragments, pairwise: [bh][kb][pi(32)][lane(32)] of uint4
__device__ uint2 g_kpk[64*NKB*64*32];
__device__ uint2 g_vpk[64*NKB*64*32];

__device__ __forceinline__ uint32_t f2tf32(float f) {
    uint32_t u;
    asm("cvt.rna.tf32.f32 %0, %1;" : "=r"(u) : "f"(f));
    return u;
}

__device__ __forceinline__ void mma_tf32(
    float* c, uint32_t a0, uint32_t a1, uint32_t a2, uint32_t a3,
    uint32_t b0, uint32_t b1)
{
    asm volatile(
        "mma.sync.aligned.m16n8k8.row.col.f32.tf32.tf32.f32 "
        "{%0,%1,%2,%3}, {%4,%5,%6,%7}, {%8,%9}, {%0,%1,%2,%3};"
        : "+f"(c[0]), "+f"(c[1]), "+f"(c[2]), "+f"(c[3])
        : "r"(a0), "r"(a1), "r"(a2), "r"(a3), "r"(b0), "r"(b1));
}

__device__ __forceinline__ uint32_t smem_u32(const void* p) {
    uint32_t a;
    asm("{ .reg .u64 t; cvta.to.shared.u64 t, %1; cvt.u32.u64 %0, t; }"
        : "=r"(a) : "l"(p));
    return a;
}

#define LDSM4(r0, r1, r2, r3, addr) \
    asm volatile("ldmatrix.sync.aligned.m8n8.x4.shared.b16 {%0,%1,%2,%3}, [%4];" \
                 : "=r"(r0), "=r"(r1), "=r"(r2), "=r"(r3) : "r"(addr))

#define CP_ASYNC16(dst_u32, src) \
    asm volatile("cp.async.cg.shared.global [%0], [%1], 16;" \
                 :: "r"(dst_u32), "l"(src) : "memory")
#define CP_COMMIT() asm volatile("cp.async.commit_group;" ::: "memory")
#define CP_WAIT2()  asm volatile("cp.async.wait_group 2;" ::: "memory")

// ============================================================================
// Round fp32 -> tf32 (RNA), stored as fp32 bits.
// ============================================================================
__global__ void round_tf32(const float* __restrict__ in, float* __restrict__ out,
                           int n)
{
    int i = (blockIdx.x * blockDim.x + threadIdx.x) * 4;
    if (i >= n) return;
    float4 v = *(const float4*)(in + i);
    v.x = __uint_as_float(f2tf32(v.x));
    v.y = __uint_as_float(f2tf32(v.y));
    v.z = __uint_as_float(f2tf32(v.z));
    v.w = __uint_as_float(f2tf32(v.w));
    *(float4*)(out + i) = v;
}

// ============================================================================
// cp.async 4-stage tf32 GEMM with ldmatrix fragment loads (unchanged R8).
// ============================================================================
#define GP        20
#define SSTRIDE   (2*128*GP)           // floats per stage = 5120
#define NSTAGE    4
#define GEMM_SMEM (NSTAGE*SSTRIDE*4)   // 81920 B
#define NCH       (Dv/16)              // 64

template<int MODE>
__global__ __launch_bounds__(256, 2)
void gemm_cp(const float* __restrict__ A, const float* __restrict__ Bw,
             float* __restrict__ C)
{
    extern __shared__ float smf[];
    const uint32_t sb32 = smem_u32(smf);

    const int tid  = threadIdx.x;
    const int wid  = tid >> 5, lane = tid & 31;
    const int gid  = lane >> 2, tg = lane & 3;
    const int wm   = (wid >> 2) * 64;
    const int wn   = (wid & 3) * 32;
    const int m0   = blockIdx.y * 128, n0 = blockIdx.x * 128;

    const int r0 = tid >> 2, c4 = (tid & 3) * 4;
    const float* gA0 = A  + (size_t)(m0 + r0) * Dv + c4;
    const float* gA1 = gA0 + (size_t)64 * Dv;
    const float* gB0 = Bw + (size_t)(n0 + r0) * Dv + c4;
    const float* gB1 = gB0 + (size_t)64 * Dv;
    const uint32_t dA0 = sb32 + (r0*GP + c4) * 4;
    const uint32_t dA1 = dA0 + 64*GP*4;
    const uint32_t dB0 = dA0 + 2560*4;
    const uint32_t dB1 = dB0 + 64*GP*4;

    const int lrow = lane & 7, lsel = lane >> 3;
    uint32_t a_addr[4], b_addr[2];
    {
        const int arow = wm + ((lsel & 1) ? 8 : 0) + lrow;
        const int acol = (lsel >> 1) * 4;
        #pragma unroll
        for (int mi = 0; mi < 4; mi++)
            a_addr[mi] = sb32 + ((arow + mi*16)*GP + acol) * 4;
        const int bcol = (lsel & 1) * 4;
        #pragma unroll
        for (int p = 0; p < 2; p++) {
            const int brow = wn + (p*2 + (lsel >> 1))*8 + lrow;
            b_addr[p] = sb32 + 2560*4 + (brow*GP + bcol) * 4;
        }
    }

    float acc[4][4][4];
    #pragma unroll
    for (int i = 0; i < 4; i++)
        #pragma unroll
        for (int j = 0; j < 4; j++)
            #pragma unroll
            for (int r = 0; r < 4; r++) acc[i][j][r] = 0.f;

    #pragma unroll
    for (int p = 0; p < NSTAGE-1; p++) {
        const uint32_t so = p * SSTRIDE * 4;
        const int ko = p * 16;
        CP_ASYNC16(dA0 + so, gA0 + ko);
        CP_ASYNC16(dA1 + so, gA1 + ko);
        CP_ASYNC16(dB0 + so, gB0 + ko);
        CP_ASYNC16(dB1 + so, gB1 + ko);
        CP_COMMIT();
    }

    int st = 0;
    for (int ch = 0; ch < NCH; ++ch) {
        CP_WAIT2();
        __syncthreads();

        if (ch + NSTAGE-1 < NCH) {
            const uint32_t so = ((st + NSTAGE-1) & (NSTAGE-1)) * SSTRIDE * 4;
            const int ko = (ch + NSTAGE-1) * 16;
            CP_ASYNC16(dA0 + so, gA0 + ko);
            CP_ASYNC16(dA1 + so, gA1 + ko);
            CP_ASYNC16(dB0 + so, gB0 + ko);
            CP_ASYNC16(dB1 + so, gB1 + ko);
        }
        CP_COMMIT();

        const uint32_t stoff = st * SSTRIDE * 4;
        #pragma unroll
        for (int ks = 0; ks < 2; ks++) {
            const uint32_t ko = stoff + ks * 32;
            uint32_t af[4][4], bf[4][2];
            #pragma unroll
            for (int mi = 0; mi < 4; mi++)
                LDSM4(af[mi][0], af[mi][1], af[mi][2], af[mi][3], a_addr[mi] + ko);
            #pragma unroll
            for (int p = 0; p < 2; p++)
                LDSM4(bf[2*p][0], bf[2*p][1], bf[2*p+1][0], bf[2*p+1][1],
                      b_addr[p] + ko);
            #pragma unroll
            for (int mi = 0; mi < 4; mi++)
                #pragma unroll
                for (int ni = 0; ni < 4; ni++)
                    mma_tf32(acc[mi][ni],
                             af[mi][0], af[mi][1], af[mi][2], af[mi][3],
                             bf[ni][0], bf[ni][1]);
        }
        st = (st + 1) & (NSTAGE - 1);
    }

    #pragma unroll
    for (int mi = 0; mi < 4; mi++) {
        #pragma unroll
        for (int half = 0; half < 2; half++) {
            const int m = m0 + wm + mi * 16 + gid + half * 8;
            const int bb = m >> 11, trow = m & (Tv - 1);
            #pragma unroll
            for (int ni = 0; ni < 4; ni++) {
                const int n = n0 + wn + ni * 8 + tg * 2;
                float2 val;
                val.x = acc[mi][ni][half * 2 + 0];
                val.y = acc[mi][ni][half * 2 + 1];
                if (MODE == 0) {
                    const int wh = n >> 10;
                    const int d  = n & (Dv - 1);
                    const int h  = d >> 6, dd = d & 63;
                    float* dst = ((wh == 0) ? g_q : (wh == 1) ? g_k : g_v)
                               + ((size_t)(bb * Hv + h) * Tv + trow) * DHv + dd;
                    *(float2*)dst = val;
                } else {
                    *(float2*)(C + (size_t)m * Dv + n) = val;
                }
            }
        }
    }
}

// ============================================================================
// RoPE on g_q only (K rope fused into pack_kv).
// ============================================================================
__global__ void rope_q(const float* __restrict__ cosT,
                       const float* __restrict__ sinT)
{
    int gid = blockIdx.x * blockDim.x + threadIdx.x;
    if (gid >= Bv*Hv*Tv*HALFv) return;
    int i   = gid & (HALFv - 1);
    int row = gid >> 5;
    int t   = row & (Tv - 1);
    float c = cosT[t*HALFv + i];
    float s = sinT[t*HALFv + i];

    float* qp = g_q + (size_t)row * DHv;
    float q1 = qp[i], q2 = qp[i + HALFv];
    qp[i]          = q1*c - q2*s;
    qp[i + HALFv]  = q1*s + q2*c;
}

// ============================================================================
// Pack K (RoPE fused, tf32) and V into pairwise mma b-fragment order.
// ============================================================================
__global__ __launch_bounds__(256)
void pack_kv(const float* __restrict__ cosT, const float* __restrict__ sinT)
{
    const int kb = blockIdx.x, bh = blockIdx.y;
    const size_t base = ((size_t)(bh * NKB + kb)) * 2048;   // uint2 units
    const size_t rowbase = (size_t)bh * Tv + kb * 64;

    #pragma unroll
    for (int i = 0; i < 8; i++) {
        int e = threadIdx.x + i * 256;      // 0..2047
        int lane = e & 31, fi = e >> 5;
        int gid = lane >> 2, tg = lane & 3;
        int ks = fi >> 3, nf = fi & 7;

        // ---- K fragment with fused RoPE ----
        {
            const int trow = kb*64 + nf*8 + gid;
            const float* kp = g_k + (rowbase + nf*8 + gid) * DHv;
            const int dd = ks*8 + tg;
            float r0, r1;
            if (dd < HALFv) {
                float c0 = cosT[trow*HALFv + dd],     s0 = sinT[trow*HALFv + dd];
                float c1 = cosT[trow*HALFv + dd + 4], s1 = sinT[trow*HALFv + dd + 4];
                r0 = kp[dd]     * c0 - kp[dd + HALFv]     * s0;
                r1 = kp[dd + 4] * c1 - kp[dd + 4 + HALFv] * s1;
            } else {
                const int i0 = dd - HALFv;
                float c0 = cosT[trow*HALFv + i0],     s0 = sinT[trow*HALFv + i0];
                float c1 = cosT[trow*HALFv + i0 + 4], s1 = sinT[trow*HALFv + i0 + 4];
                r0 = kp[i0]     * s0 + kp[dd]     * c0;
                r1 = kp[i0 + 4] * s1 + kp[dd + 4] * c1;
            }
            const int pi = ks*4 + (nf >> 1);
            g_kpk[base + ((size_t)pi*32 + lane)*2 + (nf & 1)] =
                make_uint2(f2tf32(r0), f2tf32(r1));
        }

        // ---- V fragment ----
        {
            const float* vp = g_v + (rowbase + ks*8 + tg) * DHv + nf*8 + gid;
            const int pi = ks*4 + (nf >> 1);
            g_vpk[base + ((size_t)pi*32 + lane)*2 + (nf & 1)] =
                make_uint2(f2tf32(vp[0]), f2tf32(vp[4*DHv]));
        }
    }
}

// ============================================================================
// Flash attention: 4 warps x 32 q-rows (2 m-frags/warp), key-tile 64/iter.
// Barrier-free mainloop, pairwise-packed K/V fragments (LDG.128).
// QK^T 2-term split, PV tf32. Diagonal kept in denom, zeroed in P.
// Smem 96KB: Qhip[(w*2+mi)*8+ks][32]u4 @0 (32KB), Qlop @32768, Ppk @65536.
// ============================================================================
#define ATTN_SMEM (3*32768)

__global__ __launch_bounds__(128, 2)
void attn_mma()
{
    extern __shared__ char sm[];
    uint4*  Qhip = (uint4*)sm;
    uint4*  Qlop = (uint4*)(sm + 32768);
    float4* Ppk  = (float4*)(sm + 65536);

    const int qb = (int)gridDim.x - 1 - (int)blockIdx.x;  // heavy tiles first
    const int bh = blockIdx.y;
    const int tid = threadIdx.x;
    const int w = tid >> 5, lane = tid & 31;
    const int gid = lane >> 2, tg = lane & 3;

    // warp covers rows [qb*128 + 32w, +32): m-frag mi at rows +16*mi
    int rowA[2], rowB[2];
    #pragma unroll
    for (int mi = 0; mi < 2; mi++) {
        rowA[mi] = qb*128 + 32*w + 16*mi + gid;
        rowB[mi] = rowA[mi] + 8;
    }

    // ---- Q fragments (scaled, hi/lo) -> warp-private smem ----
    #pragma unroll
    for (int mi = 0; mi < 2; mi++) {
        const float* qA = g_q + ((size_t)bh*Tv + rowA[mi]) * DHv + tg;
        const float* qB = qA + 8 * DHv;
        #pragma unroll
        for (int ks = 0; ks < 8; ks++) {
            float q0 = qA[ks*8    ] * 0.125f;
            float q1 = qB[ks*8    ] * 0.125f;
            float q2 = qA[ks*8 + 4] * 0.125f;
            float q3 = qB[ks*8 + 4] * 0.125f;
            uint32_t h0 = f2tf32(q0), h1 = f2tf32(q1);
            uint32_t h2 = f2tf32(q2), h3 = f2tf32(q3);
            const int fs = ((w*2 + mi)*8 + ks)*32 + lane;
            Qhip[fs] = make_uint4(h0, h1, h2, h3);
            Qlop[fs] = make_uint4(f2tf32(q0 - __uint_as_float(h0)),
                                  f2tf32(q1 - __uint_as_float(h1)),
                                  f2tf32(q2 - __uint_as_float(h2)),
                                  f2tf32(q3 - __uint_as_float(h3)));
        }
    }
    __syncwarp();

    float O[2][8][4];
    #pragma unroll
    for (int mi = 0; mi < 2; mi++)
        #pragma unroll
        for (int d = 0; d < 8; d++)
            #pragma unroll
            for (int r = 0; r < 4; r++) O[mi][d][r] = 0.f;
    float mA[2] = {-1e30f, -1e30f}, mB[2] = {-1e30f, -1e30f};
    float lA[2] = {0.f, 0.f},       lB[2] = {0.f, 0.f};

    const uint4* kpk = (const uint4*)g_kpk + (size_t)bh * NKB * 1024 + lane;
    const uint4* vpk = (const uint4*)g_vpk + (size_t)bh * NKB * 1024 + lane;

    const int niter = 2 * (qb + 1);
    for (int j = 0; j < niter; j++) {
        const int k0g = j * 64;
        const uint4* kt = kpk + (size_t)j * 1024;
        const uint4* vt = vpk + (size_t)j * 1024;

        // ---- S = Q K^T (2-term split), 2 m-frags ----
        float S[2][8][4];
        #pragma unroll
        for (int mi = 0; mi < 2; mi++)
            #pragma unroll
            for (int nf = 0; nf < 8; nf++)
                #pragma unroll
                for (int r = 0; r < 4; r++) S[mi][nf][r] = 0.f;
        #pragma unroll
        for (int ks = 0; ks < 8; ks++) {
            uint4 qh0 = Qhip[((w*2 + 0)*8 + ks)*32 + lane];
            uint4 ql0 = Qlop[((w*2 + 0)*8 + ks)*32 + lane];
            uint4 qh1 = Qhip[((w*2 + 1)*8 + ks)*32 + lane];
            uint4 ql1 = Qlop[((w*2 + 1)*8 + ks)*32 + lane];
            #pragma unroll
            for (int nf2 = 0; nf2 < 4; nf2++) {
                uint4 kf = kt[(ks*4 + nf2)*32];
                mma_tf32(S[0][2*nf2    ], qh0.x, qh0.y, qh0.z, qh0.w, kf.x, kf.y);
                mma_tf32(S[0][2*nf2    ], ql0.x, ql0.y, ql0.z, ql0.w, kf.x, kf.y);
                mma_tf32(S[0][2*nf2 + 1], qh0.x, qh0.y, qh0.z, qh0.w, kf.z, kf.w);
                mma_tf32(S[0][2*nf2 + 1], ql0.x, ql0.y, ql0.z, ql0.w, kf.z, kf.w);
                mma_tf32(S[1][2*nf2    ], qh1.x, qh1.y, qh1.z, qh1.w, kf.x, kf.y);
                mma_tf32(S[1][2*nf2    ], ql1.x, ql1.y, ql1.z, ql1.w, kf.x, kf.y);
                mma_tf32(S[1][2*nf2 + 1], qh1.x, qh1.y, qh1.z, qh1.w, kf.z, kf.w);
                mma_tf32(S[1][2*nf2 + 1], ql1.x, ql1.y, ql1.z, ql1.w, kf.z, kf.w);
            }
        }

        // ---- mask + online softmax + pack P (per m-frag) ----
        #pragma unroll
        for (int mi = 0; mi < 2; mi++) {
            float mxA = -1e30f, mxB = -1e30f;
            #pragma unroll
            for (int nf = 0; nf < 8; nf++) {
                const int cA = k0g + nf*8 + 2*tg, cB = cA + 1;
                if (cA > rowA[mi]) S[mi][nf][0] = -1e30f;
                if (cB > rowA[mi]) S[mi][nf][1] = -1e30f;
                if (cA > rowB[mi]) S[mi][nf][2] = -1e30f;
                if (cB > rowB[mi]) S[mi][nf][3] = -1e30f;
                mxA = fmaxf(mxA, fmaxf(S[mi][nf][0], S[mi][nf][1]));
                mxB = fmaxf(mxB, fmaxf(S[mi][nf][2], S[mi][nf][3]));
            }
            mxA = fmaxf(mxA, __shfl_xor_sync(0xffffffffu, mxA, 1));
            mxA = fmaxf(mxA, __shfl_xor_sync(0xffffffffu, mxA, 2));
            mxB = fmaxf(mxB, __shfl_xor_sync(0xffffffffu, mxB, 1));
            mxB = fmaxf(mxB, __shfl_xor_sync(0xffffffffu, mxB, 2));
            const float mnA = fmaxf(mA[mi], mxA), mnB = fmaxf(mB[mi], mxB);
            const float corrA = __expf(mA[mi] - mnA), corrB = __expf(mB[mi] - mnB);

            float sA = 0.f, sB = 0.f;
            #pragma unroll
            for (int nf = 0; nf < 8; nf++) {
                const int cA = k0g + nf*8 + 2*tg, cB = cA + 1;
                float e0 = __expf(S[mi][nf][0] - mnA);
                float e1 = __expf(S[mi][nf][1] - mnA);
                float e2 = __expf(S[mi][nf][2] - mnB);
                float e3 = __expf(S[mi][nf][3] - mnB);
                sA += e0 + e1; sB += e2 + e3;
                if (cA == rowA[mi]) e0 = 0.f;
                if (cB == rowA[mi]) e1 = 0.f;
                if (cA == rowB[mi]) e2 = 0.f;
                if (cB == rowB[mi]) e3 = 0.f;
                {
                    const int c0p = 2*tg;
                    char* b = (char*)&Ppk[((w*2 + mi)*8 + nf)*32 + 4*gid + (c0p & 3)];
                    *(uint2*)(b + ((c0p < 4) ? 0 : 8)) = make_uint2(f2tf32(e0), f2tf32(e2));
                }
                {
                    const int c1p = 2*tg + 1;
                    char* b = (char*)&Ppk[((w*2 + mi)*8 + nf)*32 + 4*gid + (c1p & 3)];
                    *(uint2*)(b + ((c1p < 4) ? 0 : 8)) = make_uint2(f2tf32(e1), f2tf32(e3));
                }
            }
            sA += __shfl_xor_sync(0xffffffffu, sA, 1);
            sA += __shfl_xor_sync(0xffffffffu, sA, 2);
            sB += __shfl_xor_sync(0xffffffffu, sB, 1);
            sB += __shfl_xor_sync(0xffffffffu, sB, 2);
            lA[mi] = lA[mi] * corrA + sA;  mA[mi] = mnA;
            lB[mi] = lB[mi] * corrB + sB;  mB[mi] = mnB;
            #pragma unroll
            for (int d = 0; d < 8; d++) {
                O[mi][d][0] *= corrA; O[mi][d][1] *= corrA;
                O[mi][d][2] *= corrB; O[mi][d][3] *= corrB;
            }
        }
        __syncwarp();

        // ---- O += P V (tf32), 2 m-frags ----
        #pragma unroll
        for (int cs = 0; cs < 8; cs++) {
            uint4 a0 = *(const uint4*)&Ppk[((w*2 + 0)*8 + cs)*32 + lane];
            uint4 a1 = *(const uint4*)&Ppk[((w*2 + 1)*8 + cs)*32 + lane];
            #pragma unroll
            for (int df2 = 0; df2 < 4; df2++) {
                uint4 b = vt[(cs*4 + df2)*32];
                mma_tf32(O[0][2*df2    ], a0.x, a0.y, a0.z, a0.w, b.x, b.y);
                mma_tf32(O[0][2*df2 + 1], a0.x, a0.y, a0.z, a0.w, b.z, b.w);
                mma_tf32(O[1][2*df2    ], a1.x, a1.y, a1.z, a1.w, b.x, b.y);
                mma_tf32(O[1][2*df2 + 1], a1.x, a1.y, a1.z, a1.w, b.z, b.w);
            }
        }
        __syncwarp();
    }

    // ---- epilogue (round to tf32 for the proj GEMM) ----
    const int bb = bh >> 4, h = bh & 15;
    #pragma unroll
    for (int mi = 0; mi < 2; mi++) {
        const float inv0 = 1.f / lA[mi], inv1 = 1.f / lB[mi];
        #pragma unroll
        for (int df = 0; df < 8; df++) {
            const int col = h*64 + df*8 + 2*tg;
            float2 vA, vB;
            vA.x = __uint_as_float(f2tf32(O[mi][df][0] * inv0));
            vA.y = __uint_as_float(f2tf32(O[mi][df][1] * inv0));
            vB.x = __uint_as_float(f2tf32(O[mi][df][2] * inv1));
            vB.y = __uint_as_float(f2tf32(O[mi][df][3] * inv1));
            *(float2*)&g_attn[((size_t)bb*Tv + rowA[mi]) * Dv + col] = vA;
            *(float2*)&g_attn[((size_t)bb*Tv + rowB[mi]) * Dv + col] = vB;
        }
    }
}

// ============================================================================
extern "C" void kernel_launch(void* const* d_in, const int* in_sizes, int n_in,
                              void* d_out, int out_size)
{
    const float* x     = (const float*)d_in[0];
    const float* cosT  = (const float*)d_in[1];
    const float* sinT  = (const float*)d_in[2];
    const float* Wqkv  = (const float*)d_in[3];
    const float* Wproj = (const float*)d_in[4];

    float *attn_ptr, *xr_ptr, *wqkvr_ptr, *wprojr_ptr;
    cudaGetSymbolAddress((void**)&attn_ptr,   g_attn);
    cudaGetSymbolAddress((void**)&xr_ptr,     g_xr);
    cudaGetSymbolAddress((void**)&wqkvr_ptr,  g_wqkvr);
    cudaGetSymbolAddress((void**)&wprojr_ptr, g_wprojr);

    cudaFuncSetAttribute(attn_mma, cudaFuncAttributeMaxDynamicSharedMemorySize, ATTN_SMEM);
    cudaFuncSetAttribute(gemm_cp<0>, cudaFuncAttributeMaxDynamicSharedMemorySize, GEMM_SMEM);
    cudaFuncSetAttribute(gemm_cp<1>, cudaFuncAttributeMaxDynamicSharedMemorySize, GEMM_SMEM);

    // 0) pre-round GEMM inputs to tf32
    round_tf32<<<MROWS*Dv/1024, 256>>>(x, xr_ptr, MROWS*Dv);
    round_tf32<<<NQKV*Dv/1024, 256>>>(Wqkv, wqkvr_ptr, NQKV*Dv);
    round_tf32<<<Dv*Dv/1024, 256>>>(Wproj, wprojr_ptr, Dv*Dv);

    // 1) QKV projection, scattered into [b,h,t,dh]
    gemm_cp<0><<<dim3(NQKV/128, MROWS/128), 256, GEMM_SMEM>>>(xr_ptr, wqkvr_ptr, nullptr);
    // 2) RoPE on q (k rope fused into pack_kv)
    rope_q<<<(Bv*Hv*Tv*HALFv + 255)/256, 256>>>(cosT, sinT);
    // 3) pack K (rope fused) / V into pairwise fragment order
    pack_kv<<<dim3(NKB, Bv*Hv), 256>>>(cosT, sinT);
    // 4) causal attention (4 warps x 32 rows, barrier-free mainloop)
    attn_mma<<<dim3(Tv/128, Bv*Hv), 128, ATTN_SMEM>>>();
    // 5) output projection -> d_out
    gemm_cp<1><<<dim3(Dv/128, MROWS/128), 256, GEMM_SMEM>>>(attn_ptr, wprojr_ptr, (float*)d_out);
}

// round 12
// speedup vs baseline: 2.0596x; 1.0412x over previous
#include <cuda_runtime.h>
#include <math.h>
#include <stdint.h>

#define Bv    4
#define Tv    2048
#define Dv    1024
#define Hv    16
#define DHv   64
#define HALFv 32
#define MROWS (Bv*Tv)      // 8192
#define NQKV  (3*Dv)       // 3072
#define NKB   (Tv/64)      // 32 key tiles per bh

// ---- scratch (device globals) ----
__device__ float g_q[Bv*Hv*Tv*DHv];     // [b,h,t,dh] fp32 (RoPE'd)
__device__ float g_k[Bv*Hv*Tv*DHv];     // [b,h,t,dh] fp32 (pre-RoPE; rope fused into pack)
__device__ float g_v[Bv*Hv*Tv*DHv];
__device__ float g_attn[MROWS*Dv];      // [b,t,d], tf32-rounded by attn epilogue
__device__ float g_xr[MROWS*Dv];        // tf32-rounded x
__device__ float g_wqkvr[NQKV*Dv];      // tf32-rounded W_qkv
__device__ float g_wprojr[Dv*Dv];       // tf32-rounded W_proj
// packed fragments, pairwise: [bh][kb][pi(32)][lane(32)] of uint4 (16KB/tile)
__device__ uint2 g_kpk[64*NKB*64*32];
__device__ uint2 g_vpk[64*NKB*64*32];

__device__ __forceinline__ uint32_t f2tf32(float f) {
    uint32_t u;
    asm("cvt.rna.tf32.f32 %0, %1;" : "=r"(u) : "f"(f));
    return u;
}

__device__ __forceinline__ void mma_tf32(
    float* c, uint32_t a0, uint32_t a1, uint32_t a2, uint32_t a3,
    uint32_t b0, uint32_t b1)
{
    asm volatile(
        "mma.sync.aligned.m16n8k8.row.col.f32.tf32.tf32.f32 "
        "{%0,%1,%2,%3}, {%4,%5,%6,%7}, {%8,%9}, {%0,%1,%2,%3};"
        : "+f"(c[0]), "+f"(c[1]), "+f"(c[2]), "+f"(c[3])
        : "r"(a0), "r"(a1), "r"(a2), "r"(a3), "r"(b0), "r"(b1));
}

__device__ __forceinline__ uint32_t smem_u32(const void* p) {
    uint32_t a;
    asm("{ .reg .u64 t; cvta.to.shared.u64 t, %1; cvt.u32.u64 %0, t; }"
        : "=r"(a) : "l"(p));
    return a;
}

#define LDSM4(r0, r1, r2, r3, addr) \
    asm volatile("ldmatrix.sync.aligned.m8n8.x4.shared.b16 {%0,%1,%2,%3}, [%4];" \
                 : "=r"(r0), "=r"(r1), "=r"(r2), "=r"(r3) : "r"(addr))

#define CP_ASYNC16(dst_u32, src) \
    asm volatile("cp.async.cg.shared.global [%0], [%1], 16;" \
                 :: "r"(dst_u32), "l"(src) : "memory")
#define CP_COMMIT() asm volatile("cp.async.commit_group;" ::: "memory")
#define CP_WAIT2()  asm volatile("cp.async.wait_group 2;" ::: "memory")
#define CP_WAIT1()  asm volatile("cp.async.wait_group 1;" ::: "memory")
#define CP_WAIT0()  asm volatile("cp.async.wait_group 0;" ::: "memory")

// stage a contiguous 16KB tile into smem with 128 threads (8 x 16B each)
__device__ __forceinline__ void stage16k(uint32_t dst, const char* src, int tid) {
    #pragma unroll
    for (int p = 0; p < 8; p++)
        CP_ASYNC16(dst + tid*16 + p*2048, src + tid*16 + p*2048);
}

// ============================================================================
// Round fp32 -> tf32 (RNA), stored as fp32 bits.
// ============================================================================
__global__ void round_tf32(const float* __restrict__ in, float* __restrict__ out,
                           int n)
{
    int i = (blockIdx.x * blockDim.x + threadIdx.x) * 4;
    if (i >= n) return;
    float4 v = *(const float4*)(in + i);
    v.x = __uint_as_float(f2tf32(v.x));
    v.y = __uint_as_float(f2tf32(v.y));
    v.z = __uint_as_float(f2tf32(v.z));
    v.w = __uint_as_float(f2tf32(v.w));
    *(float4*)(out + i) = v;
}

// ============================================================================
// cp.async 4-stage tf32 GEMM with ldmatrix fragment loads (unchanged).
// ============================================================================
#define GP        20
#define SSTRIDE   (2*128*GP)           // floats per stage = 5120
#define NSTAGE    4
#define GEMM_SMEM (NSTAGE*SSTRIDE*4)   // 81920 B
#define NCH       (Dv/16)              // 64

template<int MODE>
__global__ __launch_bounds__(256, 2)
void gemm_cp(const float* __restrict__ A, const float* __restrict__ Bw,
             float* __restrict__ C)
{
    extern __shared__ float smf[];
    const uint32_t sb32 = smem_u32(smf);

    const int tid  = threadIdx.x;
    const int wid  = tid >> 5, lane = tid & 31;
    const int gid  = lane >> 2, tg = lane & 3;
    const int wm   = (wid >> 2) * 64;
    const int wn   = (wid & 3) * 32;
    const int m0   = blockIdx.y * 128, n0 = blockIdx.x * 128;

    const int r0 = tid >> 2, c4 = (tid & 3) * 4;
    const float* gA0 = A  + (size_t)(m0 + r0) * Dv + c4;
    const float* gA1 = gA0 + (size_t)64 * Dv;
    const float* gB0 = Bw + (size_t)(n0 + r0) * Dv + c4;
    const float* gB1 = gB0 + (size_t)64 * Dv;
    const uint32_t dA0 = sb32 + (r0*GP + c4) * 4;
    const uint32_t dA1 = dA0 + 64*GP*4;
    const uint32_t dB0 = dA0 + 2560*4;
    const uint32_t dB1 = dB0 + 64*GP*4;

    const int lrow = lane & 7, lsel = lane >> 3;
    uint32_t a_addr[4], b_addr[2];
    {
        const int arow = wm + ((lsel & 1) ? 8 : 0) + lrow;
        const int acol = (lsel >> 1) * 4;
        #pragma unroll
        for (int mi = 0; mi < 4; mi++)
            a_addr[mi] = sb32 + ((arow + mi*16)*GP + acol) * 4;
        const int bcol = (lsel & 1) * 4;
        #pragma unroll
        for (int p = 0; p < 2; p++) {
            const int brow = wn + (p*2 + (lsel >> 1))*8 + lrow;
            b_addr[p] = sb32 + 2560*4 + (brow*GP + bcol) * 4;
        }
    }

    float acc[4][4][4];
    #pragma unroll
    for (int i = 0; i < 4; i++)
        #pragma unroll
        for (int j = 0; j < 4; j++)
            #pragma unroll
            for (int r = 0; r < 4; r++) acc[i][j][r] = 0.f;

    #pragma unroll
    for (int p = 0; p < NSTAGE-1; p++) {
        const uint32_t so = p * SSTRIDE * 4;
        const int ko = p * 16;
        CP_ASYNC16(dA0 + so, gA0 + ko);
        CP_ASYNC16(dA1 + so, gA1 + ko);
        CP_ASYNC16(dB0 + so, gB0 + ko);
        CP_ASYNC16(dB1 + so, gB1 + ko);
        CP_COMMIT();
    }

    int st = 0;
    for (int ch = 0; ch < NCH; ++ch) {
        CP_WAIT2();
        __syncthreads();

        if (ch + NSTAGE-1 < NCH) {
            const uint32_t so = ((st + NSTAGE-1) & (NSTAGE-1)) * SSTRIDE * 4;
            const int ko = (ch + NSTAGE-1) * 16;
            CP_ASYNC16(dA0 + so, gA0 + ko);
            CP_ASYNC16(dA1 + so, gA1 + ko);
            CP_ASYNC16(dB0 + so, gB0 + ko);
            CP_ASYNC16(dB1 + so, gB1 + ko);
        }
        CP_COMMIT();

        const uint32_t stoff = st * SSTRIDE * 4;
        #pragma unroll
        for (int ks = 0; ks < 2; ks++) {
            const uint32_t ko = stoff + ks * 32;
            uint32_t af[4][4], bf[4][2];
            #pragma unroll
            for (int mi = 0; mi < 4; mi++)
                LDSM4(af[mi][0], af[mi][1], af[mi][2], af[mi][3], a_addr[mi] + ko);
            #pragma unroll
            for (int p = 0; p < 2; p++)
                LDSM4(bf[2*p][0], bf[2*p][1], bf[2*p+1][0], bf[2*p+1][1],
                      b_addr[p] + ko);
            #pragma unroll
            for (int mi = 0; mi < 4; mi++)
                #pragma unroll
                for (int ni = 0; ni < 4; ni++)
                    mma_tf32(acc[mi][ni],
                             af[mi][0], af[mi][1], af[mi][2], af[mi][3],
                             bf[ni][0], bf[ni][1]);
        }
        st = (st + 1) & (NSTAGE - 1);
    }

    #pragma unroll
    for (int mi = 0; mi < 4; mi++) {
        #pragma unroll
        for (int half = 0; half < 2; half++) {
            const int m = m0 + wm + mi * 16 + gid + half * 8;
            const int bb = m >> 11, trow = m & (Tv - 1);
            #pragma unroll
            for (int ni = 0; ni < 4; ni++) {
                const int n = n0 + wn + ni * 8 + tg * 2;
                float2 val;
                val.x = acc[mi][ni][half * 2 + 0];
                val.y = acc[mi][ni][half * 2 + 1];
                if (MODE == 0) {
                    const int wh = n >> 10;
                    const int d  = n & (Dv - 1);
                    const int h  = d >> 6, dd = d & 63;
                    float* dst = ((wh == 0) ? g_q : (wh == 1) ? g_k : g_v)
                               + ((size_t)(bb * Hv + h) * Tv + trow) * DHv + dd;
                    *(float2*)dst = val;
                } else {
                    *(float2*)(C + (size_t)m * Dv + n) = val;
                }
            }
        }
    }
}

// ============================================================================
// RoPE on g_q only (K rope fused into pack_kv).
// ============================================================================
__global__ void rope_q(const float* __restrict__ cosT,
                       const float* __restrict__ sinT)
{
    int gid = blockIdx.x * blockDim.x + threadIdx.x;
    if (gid >= Bv*Hv*Tv*HALFv) return;
    int i   = gid & (HALFv - 1);
    int row = gid >> 5;
    int t   = row & (Tv - 1);
    float c = cosT[t*HALFv + i];
    float s = sinT[t*HALFv + i];

    float* qp = g_q + (size_t)row * DHv;
    float q1 = qp[i], q2 = qp[i + HALFv];
    qp[i]          = q1*c - q2*s;
    qp[i + HALFv]  = q1*s + q2*c;
}

// ============================================================================
// Pack K (RoPE fused, tf32) and V into pairwise mma b-fragment order.
// ============================================================================
__global__ __launch_bounds__(256)
void pack_kv(const float* __restrict__ cosT, const float* __restrict__ sinT)
{
    const int kb = blockIdx.x, bh = blockIdx.y;
    const size_t base = ((size_t)(bh * NKB + kb)) * 2048;   // uint2 units
    const size_t rowbase = (size_t)bh * Tv + kb * 64;

    #pragma unroll
    for (int i = 0; i < 8; i++) {
        int e = threadIdx.x + i * 256;      // 0..2047
        int lane = e & 31, fi = e >> 5;
        int gid = lane >> 2, tg = lane & 3;
        int ks = fi >> 3, nf = fi & 7;

        // ---- K fragment with fused RoPE ----
        {
            const int trow = kb*64 + nf*8 + gid;
            const float* kp = g_k + (rowbase + nf*8 + gid) * DHv;
            const int dd = ks*8 + tg;
            float r0, r1;
            if (dd < HALFv) {
                float c0 = cosT[trow*HALFv + dd],     s0 = sinT[trow*HALFv + dd];
                float c1 = cosT[trow*HALFv + dd + 4], s1 = sinT[trow*HALFv + dd + 4];
                r0 = kp[dd]     * c0 - kp[dd + HALFv]     * s0;
                r1 = kp[dd + 4] * c1 - kp[dd + 4 + HALFv] * s1;
            } else {
                const int i0 = dd - HALFv;
                float c0 = cosT[trow*HALFv + i0],     s0 = sinT[trow*HALFv + i0];
                float c1 = cosT[trow*HALFv + i0 + 4], s1 = sinT[trow*HALFv + i0 + 4];
                r0 = kp[i0]     * s0 + kp[dd]     * c0;
                r1 = kp[i0 + 4] * s1 + kp[dd + 4] * c1;
            }
            const int pi = ks*4 + (nf >> 1);
            g_kpk[base + ((size_t)pi*32 + lane)*2 + (nf & 1)] =
                make_uint2(f2tf32(r0), f2tf32(r1));
        }

        // ---- V fragment ----
        {
            const float* vp = g_v + (rowbase + ks*8 + tg) * DHv + nf*8 + gid;
            const int pi = ks*4 + (nf >> 1);
            g_vpk[base + ((size_t)pi*32 + lane)*2 + (nf & 1)] =
                make_uint2(f2tf32(vp[0]), f2tf32(vp[4*DHv]));
        }
    }
}

// ============================================================================
// Flash attention: 4 warps x 32 q-rows, K/V tiles cp.async-staged into smem
// with one-phase prefetch distance. QK^T 2-term split, PV tf32.
// Smem 96KB: Qlo 32K @0, Ppk 32K @32768, Ksm 16K @65536, Vsm 16K @81920.
// Q-hi fragments live in registers.
// ============================================================================
#define ATTN_SMEM (96*1024)

__global__ __launch_bounds__(128, 2)
void attn_mma()
{
    extern __shared__ char sm[];
    uint4*  Qlop = (uint4*)sm;                 // 32KB
    float4* Ppk  = (float4*)(sm + 32768);      // 32KB
    uint4*  Ksm  = (uint4*)(sm + 65536);       // 16KB
    uint4*  Vsm  = (uint4*)(sm + 81920);       // 16KB
    const uint32_t sb = smem_u32(sm);
    const uint32_t ksm_a = sb + 65536, vsm_a = sb + 81920;

    const int qb = (int)gridDim.x - 1 - (int)blockIdx.x;  // heavy tiles first
    const int bh = blockIdx.y;
    const int tid = threadIdx.x;
    const int w = tid >> 5, lane = tid & 31;
    const int gid = lane >> 2, tg = lane & 3;

    int rowA[2], rowB[2];
    #pragma unroll
    for (int mi = 0; mi < 2; mi++) {
        rowA[mi] = qb*128 + 32*w + 16*mi + gid;
        rowB[mi] = rowA[mi] + 8;
    }

    // ---- Q fragments: hi -> registers, lo -> smem ----
    uint4 qh[2][8];
    #pragma unroll
    for (int mi = 0; mi < 2; mi++) {
        const float* qA = g_q + ((size_t)bh*Tv + rowA[mi]) * DHv + tg;
        const float* qB = qA + 8 * DHv;
        #pragma unroll
        for (int ks = 0; ks < 8; ks++) {
            float q0 = qA[ks*8    ] * 0.125f;
            float q1 = qB[ks*8    ] * 0.125f;
            float q2 = qA[ks*8 + 4] * 0.125f;
            float q3 = qB[ks*8 + 4] * 0.125f;
            uint32_t h0 = f2tf32(q0), h1 = f2tf32(q1);
            uint32_t h2 = f2tf32(q2), h3 = f2tf32(q3);
            qh[mi][ks] = make_uint4(h0, h1, h2, h3);
            Qlop[((w*2 + mi)*8 + ks)*32 + lane] =
                make_uint4(f2tf32(q0 - __uint_as_float(h0)),
                           f2tf32(q1 - __uint_as_float(h1)),
                           f2tf32(q2 - __uint_as_float(h2)),
                           f2tf32(q3 - __uint_as_float(h3)));
        }
    }

    float O[2][8][4];
    #pragma unroll
    for (int mi = 0; mi < 2; mi++)
        #pragma unroll
        for (int d = 0; d < 8; d++)
            #pragma unroll
            for (int r = 0; r < 4; r++) O[mi][d][r] = 0.f;
    float mA[2] = {-1e30f, -1e30f}, mB[2] = {-1e30f, -1e30f};
    float lA[2] = {0.f, 0.f},       lB[2] = {0.f, 0.f};

    const char* kbase = (const char*)g_kpk + (size_t)bh * (NKB * 16384);
    const char* vbase = (const char*)g_vpk + (size_t)bh * (NKB * 16384);
    const int niter = 2 * (qb + 1);

    // prologue: stage tile 0
    stage16k(ksm_a, kbase, tid); CP_COMMIT();
    stage16k(vsm_a, vbase, tid); CP_COMMIT();

    for (int j = 0; j < niter; j++) {
        const int k0g = j * 64;
        CP_WAIT1();            // K(j) landed (V(j) may be in flight)
        __syncthreads();       // Ksm visible to all warps

        // ---- S = Q K^T (2-term split), 2 m-frags ----
        float S[2][8][4];
        #pragma unroll
        for (int mi = 0; mi < 2; mi++)
            #pragma unroll
            for (int nf = 0; nf < 8; nf++)
                #pragma unroll
                for (int r = 0; r < 4; r++) S[mi][nf][r] = 0.f;
        #pragma unroll
        for (int ks = 0; ks < 8; ks++) {
            uint4 ql0 = Qlop[((w*2 + 0)*8 + ks)*32 + lane];
            uint4 ql1 = Qlop[((w*2 + 1)*8 + ks)*32 + lane];
            #pragma unroll
            for (int nf2 = 0; nf2 < 4; nf2++) {
                uint4 kf = Ksm[(ks*4 + nf2)*32 + lane];
                mma_tf32(S[0][2*nf2    ], qh[0][ks].x, qh[0][ks].y, qh[0][ks].z, qh[0][ks].w, kf.x, kf.y);
                mma_tf32(S[0][2*nf2    ], ql0.x, ql0.y, ql0.z, ql0.w, kf.x, kf.y);
                mma_tf32(S[0][2*nf2 + 1], qh[0][ks].x, qh[0][ks].y, qh[0][ks].z, qh[0][ks].w, kf.z, kf.w);
                mma_tf32(S[0][2*nf2 + 1], ql0.x, ql0.y, ql0.z, ql0.w, kf.z, kf.w);
                mma_tf32(S[1][2*nf2    ], qh[1][ks].x, qh[1][ks].y, qh[1][ks].z, qh[1][ks].w, kf.x, kf.y);
                mma_tf32(S[1][2*nf2    ], ql1.x, ql1.y, ql1.z, ql1.w, kf.x, kf.y);
                mma_tf32(S[1][2*nf2 + 1], qh[1][ks].x, qh[1][ks].y, qh[1][ks].z, qh[1][ks].w, kf.z, kf.w);
                mma_tf32(S[1][2*nf2 + 1], ql1.x, ql1.y, ql1.z, ql1.w, kf.z, kf.w);
            }
        }

        // ---- mask + online softmax + pack P (per m-frag) ----
        #pragma unroll
        for (int mi = 0; mi < 2; mi++) {
            float mxA = -1e30f, mxB = -1e30f;
            #pragma unroll
            for (int nf = 0; nf < 8; nf++) {
                const int cA = k0g + nf*8 + 2*tg, cB = cA + 1;
                if (cA > rowA[mi]) S[mi][nf][0] = -1e30f;
                if (cB > rowA[mi]) S[mi][nf][1] = -1e30f;
                if (cA > rowB[mi]) S[mi][nf][2] = -1e30f;
                if (cB > rowB[mi]) S[mi][nf][3] = -1e30f;
                mxA = fmaxf(mxA, fmaxf(S[mi][nf][0], S[mi][nf][1]));
                mxB = fmaxf(mxB, fmaxf(S[mi][nf][2], S[mi][nf][3]));
            }
            mxA = fmaxf(mxA, __shfl_xor_sync(0xffffffffu, mxA, 1));
            mxA = fmaxf(mxA, __shfl_xor_sync(0xffffffffu, mxA, 2));
            mxB = fmaxf(mxB, __shfl_xor_sync(0xffffffffu, mxB, 1));
            mxB = fmaxf(mxB, __shfl_xor_sync(0xffffffffu, mxB, 2));
            const float mnA = fmaxf(mA[mi], mxA), mnB = fmaxf(mB[mi], mxB);
            const float corrA = __expf(mA[mi] - mnA), corrB = __expf(mB[mi] - mnB);

            float sA = 0.f, sB = 0.f;
            #pragma unroll
            for (int nf = 0; nf < 8; nf++) {
                const int cA = k0g + nf*8 + 2*tg, cB = cA + 1;
                float e0 = __expf(S[mi][nf][0] - mnA);
                float e1 = __expf(S[mi][nf][1] - mnA);
                float e2 = __expf(S[mi][nf][2] - mnB);
                float e3 = __expf(S[mi][nf][3] - mnB);
                sA += e0 + e1; sB += e2 + e3;
                if (cA == rowA[mi]) e0 = 0.f;
                if (cB == rowA[mi]) e1 = 0.f;
                if (cA == rowB[mi]) e2 = 0.f;
                if (cB == rowB[mi]) e3 = 0.f;
                {
                    const int c0p = 2*tg;
                    char* b = (char*)&Ppk[((w*2 + mi)*8 + nf)*32 + 4*gid + (c0p & 3)];
                    *(uint2*)(b + ((c0p < 4) ? 0 : 8)) = make_uint2(f2tf32(e0), f2tf32(e2));
                }
                {
                    const int c1p = 2*tg + 1;
                    char* b = (char*)&Ppk[((w*2 + mi)*8 + nf)*32 + 4*gid + (c1p & 3)];
                    *(uint2*)(b + ((c1p < 4) ? 0 : 8)) = make_uint2(f2tf32(e1), f2tf32(e3));
                }
            }
            sA += __shfl_xor_sync(0xffffffffu, sA, 1);
            sA += __shfl_xor_sync(0xffffffffu, sA, 2);
            sB += __shfl_xor_sync(0xffffffffu, sB, 1);
            sB += __shfl_xor_sync(0xffffffffu, sB, 2);
            lA[mi] = lA[mi] * corrA + sA;  mA[mi] = mnA;
            lB[mi] = lB[mi] * corrB + sB;  mB[mi] = mnB;
            #pragma unroll
            for (int d = 0; d < 8; d++) {
                O[mi][d][0] *= corrA; O[mi][d][1] *= corrA;
                O[mi][d][2] *= corrB; O[mi][d][3] *= corrB;
            }
        }

        CP_WAIT0();            // V(j) landed
        __syncthreads();       // Ksm free + Vsm visible (+ Ppk ordering)
        if (j + 1 < niter) {   // prefetch K(j+1) while PV runs
            stage16k(ksm_a, kbase + (size_t)(j + 1) * 16384, tid);
            CP_COMMIT();
        }

        // ---- O += P V (tf32), 2 m-frags ----
        #pragma unroll
        for (int cs = 0; cs < 8; cs++) {
            uint4 a0 = *(const uint4*)&Ppk[((w*2 + 0)*8 + cs)*32 + lane];
            uint4 a1 = *(const uint4*)&Ppk[((w*2 + 1)*8 + cs)*32 + lane];
            #pragma unroll
            for (int df2 = 0; df2 < 4; df2++) {
                uint4 b = Vsm[(cs*4 + df2)*32 + lane];
                mma_tf32(O[0][2*df2    ], a0.x, a0.y, a0.z, a0.w, b.x, b.y);
                mma_tf32(O[0][2*df2 + 1], a0.x, a0.y, a0.z, a0.w, b.z, b.w);
                mma_tf32(O[1][2*df2    ], a1.x, a1.y, a1.z, a1.w, b.x, b.y);
                mma_tf32(O[1][2*df2 + 1], a1.x, a1.y, a1.z, a1.w, b.z, b.w);
            }
        }

        __syncthreads();       // Vsm free
        if (j + 1 < niter) {   // prefetch V(j+1)
            stage16k(vsm_a, vbase + (size_t)(j + 1) * 16384, tid);
            CP_COMMIT();
        }
    }

    // ---- epilogue (round to tf32 for the proj GEMM) ----
    const int bb = bh >> 4, h = bh & 15;
    #pragma unroll
    for (int mi = 0; mi < 2; mi++) {
        const float inv0 = 1.f / lA[mi], inv1 = 1.f / lB[mi];
        #pragma unroll
        for (int df = 0; df < 8; df++) {
            const int col = h*64 + df*8 + 2*tg;
            float2 vA, vB;
            vA.x = __uint_as_float(f2tf32(O[mi][df][0] * inv0));
            vA.y = __uint_as_float(f2tf32(O[mi][df][1] * inv0));
            vB.x = __uint_as_float(f2tf32(O[mi][df][2] * inv1));
            vB.y = __uint_as_float(f2tf32(O[mi][df][3] * inv1));
            *(float2*)&g_attn[((size_t)bb*Tv + rowA[mi]) * Dv + col] = vA;
            *(float2*)&g_attn[((size_t)bb*Tv + rowB[mi]) * Dv + col] = vB;
        }
    }
}

// ============================================================================
extern "C" void kernel_launch(void* const* d_in, const int* in_sizes, int n_in,
                              void* d_out, int out_size)
{
    const float* x     = (const float*)d_in[0];
    const float* cosT  = (const float*)d_in[1];
    const float* sinT  = (const float*)d_in[2];
    const float* Wqkv  = (const float*)d_in[3];
    const float* Wproj = (const float*)d_in[4];

    float *attn_ptr, *xr_ptr, *wqkvr_ptr, *wprojr_ptr;
    cudaGetSymbolAddress((void**)&attn_ptr,   g_attn);
    cudaGetSymbolAddress((void**)&xr_ptr,     g_xr);
    cudaGetSymbolAddress((void**)&wqkvr_ptr,  g_wqkvr);
    cudaGetSymbolAddress((void**)&wprojr_ptr, g_wprojr);

    cudaFuncSetAttribute(attn_mma, cudaFuncAttributeMaxDynamicSharedMemorySize, ATTN_SMEM);
    cudaFuncSetAttribute(gemm_cp<0>, cudaFuncAttributeMaxDynamicSharedMemorySize, GEMM_SMEM);
    cudaFuncSetAttribute(gemm_cp<1>, cudaFuncAttributeMaxDynamicSharedMemorySize, GEMM_SMEM);

    // 0) pre-round GEMM inputs to tf32
    round_tf32<<<MROWS*Dv/1024, 256>>>(x, xr_ptr, MROWS*Dv);
    round_tf32<<<NQKV*Dv/1024, 256>>>(Wqkv, wqkvr_ptr, NQKV*Dv);
    round_tf32<<<Dv*Dv/1024, 256>>>(Wproj, wprojr_ptr, Dv*Dv);

    // 1) QKV projection, scattered into [b,h,t,dh]
    gemm_cp<0><<<dim3(NQKV/128, MROWS/128), 256, GEMM_SMEM>>>(xr_ptr, wqkvr_ptr, nullptr);
    // 2) RoPE on q (k rope fused into pack_kv)
    rope_q<<<(Bv*Hv*Tv*HALFv + 255)/256, 256>>>(cosT, sinT);
    // 3) pack K (rope fused) / V into pairwise fragment order
    pack_kv<<<dim3(NKB, Bv*Hv), 256>>>(cosT, sinT);
    // 4) causal attention (cp.async-staged K/V, one-phase prefetch)
    attn_mma<<<dim3(Tv/128, Bv*Hv), 128, ATTN_SMEM>>>();
    // 5) output projection -> d_out
    gemm_cp<1><<<dim3(Dv/128, MROWS/128), 256, GEMM_SMEM>>>(attn_ptr, wprojr_ptr, (float*)d_out);
}